// round 6
// baseline (speedup 1.0000x reference)
#include <cuda_runtime.h>
#include <math.h>
#include <cstdint>

#define DIMD   1024
#define HEADS  16
#define DH     64
#define INNER  1024
#define BATCH  4
#define SEQ    2048
#define ROWS   (BATCH*SEQ)      // 8192
#define QKVW   (3*INNER)        // 3072

// Scratch (device globals: allocation-free contract)
__device__ float g_xn   [ROWS*DIMD];        // tf32-rounded LN output
__device__ float g_qkv  [ROWS*QKVW];        // tf32-rounded QKV
__device__ float g_att  [ROWS*INNER];       // tf32-rounded attention output
__device__ float g_wqkvT[QKVW*DIMD];        // tf32-rounded, [N][K]
__device__ float g_woutT[DIMD*INNER];       // tf32-rounded, [N][K]

__device__ __forceinline__ uint32_t cvt_tf32(float f) {
    uint32_t r;
    asm("cvt.rna.tf32.f32 %0, %1;" : "=r"(r) : "f"(f));
    return r;
}
__device__ __forceinline__ float cvt_tf32_f(float f) {
    return __uint_as_float(cvt_tf32(f));
}

__device__ __forceinline__ void mma_tf32_16x8x8(float* d, const uint32_t* a,
                                                const uint32_t* b) {
    asm volatile(
        "mma.sync.aligned.m16n8k8.row.col.f32.tf32.tf32.f32 "
        "{%0,%1,%2,%3}, {%4,%5,%6,%7}, {%8,%9}, {%0,%1,%2,%3};"
        : "+f"(d[0]), "+f"(d[1]), "+f"(d[2]), "+f"(d[3])
        : "r"(a[0]), "r"(a[1]), "r"(a[2]), "r"(a[3]), "r"(b[0]), "r"(b[1]));
}

__device__ __forceinline__ void cp_async16(uint32_t smem_dst, const void* gmem_src) {
    asm volatile("cp.async.cg.shared.global [%0], [%1], 16;" :: "r"(smem_dst), "l"(gmem_src));
}
#define CP_COMMIT() asm volatile("cp.async.commit_group;" ::: "memory")
#define CP_WAIT(n)  asm volatile("cp.async.wait_group %0;" :: "n"(n) : "memory")

// ===========================================================================
// LayerNorm: one block per row, 256 threads, float4; OUTPUT tf32-rounded.
// ===========================================================================
__global__ void ln_kernel(const float* __restrict__ x,
                          const float* __restrict__ gamma,
                          const float* __restrict__ beta,
                          float* __restrict__ out) {
    int row = blockIdx.x;
    int tid = threadIdx.x;
    const float4* xr = reinterpret_cast<const float4*>(x + (size_t)row * DIMD);
    float4 v = xr[tid];
    float s  = v.x + v.y + v.z + v.w;
    float ss = v.x*v.x + v.y*v.y + v.z*v.z + v.w*v.w;
    #pragma unroll
    for (int o = 16; o > 0; o >>= 1) {
        s  += __shfl_xor_sync(0xFFFFFFFFu, s,  o);
        ss += __shfl_xor_sync(0xFFFFFFFFu, ss, o);
    }
    __shared__ float rs[8], rq[8];
    int w = tid >> 5, l = tid & 31;
    if (l == 0) { rs[w] = s; rq[w] = ss; }
    __syncthreads();
    if (w == 0) {
        s  = (l < 8) ? rs[l] : 0.f;
        ss = (l < 8) ? rq[l] : 0.f;
        #pragma unroll
        for (int o = 4; o > 0; o >>= 1) {
            s  += __shfl_xor_sync(0xFFFFFFFFu, s,  o);
            ss += __shfl_xor_sync(0xFFFFFFFFu, ss, o);
        }
        if (l == 0) { rs[0] = s; rq[0] = ss; }
    }
    __syncthreads();
    float mu   = rs[0] * (1.0f / DIMD);
    float var  = rq[0] * (1.0f / DIMD) - mu * mu;
    float rstd = rsqrtf(var + 1e-5f);
    float4 g4 = reinterpret_cast<const float4*>(gamma)[tid];
    float4 b4 = reinterpret_cast<const float4*>(beta)[tid];
    float4 o4;
    o4.x = cvt_tf32_f((v.x - mu) * rstd * g4.x + b4.x);
    o4.y = cvt_tf32_f((v.y - mu) * rstd * g4.y + b4.y);
    o4.z = cvt_tf32_f((v.z - mu) * rstd * g4.z + b4.z);
    o4.w = cvt_tf32_f((v.w - mu) * rstd * g4.w + b4.w);
    reinterpret_cast<float4*>(out + (size_t)row * DIMD)[tid] = o4;
}

// ===========================================================================
// Transpose + round-to-tf32: in [R][Cc] -> out [Cc][R]
// ===========================================================================
__global__ void transpose_cvt(const float* __restrict__ in, float* __restrict__ out,
                              int R, int Cc) {
    __shared__ float t[32][33];
    int c0 = blockIdx.x * 32, r0 = blockIdx.y * 32;
    int x = threadIdx.x, y = threadIdx.y;   // 32 x 8
    #pragma unroll
    for (int i = 0; i < 32; i += 8)
        t[y + i][x] = in[(size_t)(r0 + y + i) * Cc + c0 + x];
    __syncthreads();
    #pragma unroll
    for (int i = 0; i < 32; i += 8) {
        float v = t[x][y + i];
        out[(size_t)(c0 + y + i) * R + r0 + x] = cvt_tf32_f(v);
    }
}

// ===========================================================================
// tf32 mma.sync GEMM, cp.async 2-stage pipeline.
// C[M,Nn] = A[M,K] @ BT[Nn,K]^T. A and BT are PRE-ROUNDED to tf32.
// CTA 128x256, BK=32, 256 threads (8 warps, 2x4), warp tile 64x64.
// ===========================================================================
#define GBK   32
#define GSTR  (GBK + 4)                    // 36 floats row stride
#define GA_ST (128 * GSTR)                 // A tile floats (4608)
#define GB_ST (256 * GSTR)                 // B tile floats (9216)
#define GEMM_SMEM ((2 * GA_ST + 2 * GB_ST) * 4)   // 110592 B

template <bool ROUND_OUT>
__global__ __launch_bounds__(256, 1)
void gemm_tf32(const float* __restrict__ A, const float* __restrict__ BT,
               float* __restrict__ C, int M, int Nn, int K) {
    extern __shared__ float sm[];

    int tid  = threadIdx.x;
    int lane = tid & 31;
    int wid  = tid >> 5;
    int wm   = wid >> 2;        // 0..1 -> m base wm*64
    int wn   = wid & 3;         // 0..3 -> n base wn*64

    const float* Ab = A  + (size_t)blockIdx.y * 128 * K;
    const float* Bb = BT + (size_t)blockIdx.x * 256 * K;

    float acc[4][8][4];
    #pragma unroll
    for (int i = 0; i < 4; i++)
        #pragma unroll
        for (int j = 0; j < 8; j++)
            #pragma unroll
            for (int k = 0; k < 4; k++) acc[i][j][k] = 0.f;

    const int nchunks = K / GBK;
    uint32_t smbase = (uint32_t)__cvta_generic_to_shared(sm);

    auto stage = [&](int c) {
        int buf = c & 1;
        uint32_t sA = smbase + (buf * GA_ST) * 4;
        uint32_t sB = smbase + ((2 * GA_ST) + buf * GB_ST) * 4;
        const float* Ac = Ab + c * GBK;
        const float* Bc = Bb + c * GBK;
        #pragma unroll
        for (int i = 0; i < 4; i++) {           // A: 128 rows x 8 float4
            int idx = i * 256 + tid;
            int m = idx >> 3, k4 = (idx & 7) << 2;
            cp_async16(sA + (m * GSTR + k4) * 4, Ac + (size_t)m * K + k4);
        }
        #pragma unroll
        for (int i = 0; i < 8; i++) {           // B: 256 rows x 8 float4
            int idx = i * 256 + tid;
            int n = idx >> 3, k4 = (idx & 7) << 2;
            cp_async16(sB + (n * GSTR + k4) * 4, Bc + (size_t)n * K + k4);
        }
    };

    stage(0);
    CP_COMMIT();

    int r  = lane >> 2;
    int cq = lane & 3;

    for (int c = 0; c < nchunks; c++) {
        if (c + 1 < nchunks) {
            stage(c + 1);
            CP_COMMIT();
            CP_WAIT(1);
        } else {
            CP_WAIT(0);
        }
        __syncthreads();

        const float* As = sm + (c & 1) * GA_ST;
        const float* Bs = sm + 2 * GA_ST + (c & 1) * GB_ST;

        #pragma unroll
        for (int ks = 0; ks < 4; ks++) {
            uint32_t a[4][4];
            #pragma unroll
            for (int mt = 0; mt < 4; mt++) {
                const float* ap = &As[(wm * 64 + mt * 16 + r) * GSTR + ks * 8 + cq];
                a[mt][0] = __float_as_uint(ap[0]);
                a[mt][1] = __float_as_uint(ap[8 * GSTR]);
                a[mt][2] = __float_as_uint(ap[4]);
                a[mt][3] = __float_as_uint(ap[8 * GSTR + 4]);
            }
            #pragma unroll
            for (int nt = 0; nt < 8; nt++) {
                uint32_t b[2];
                const float* bp = &Bs[(wn * 64 + nt * 8 + r) * GSTR + ks * 8 + cq];
                b[0] = __float_as_uint(bp[0]);
                b[1] = __float_as_uint(bp[4]);
                #pragma unroll
                for (int mt = 0; mt < 4; mt++)
                    mma_tf32_16x8x8(acc[mt][nt], a[mt], b);
            }
        }
        __syncthreads();
    }

    #pragma unroll
    for (int mt = 0; mt < 4; mt++) {
        int row0 = blockIdx.y * 128 + wm * 64 + mt * 16 + r;
        #pragma unroll
        for (int nt = 0; nt < 8; nt++) {
            int col0 = blockIdx.x * 256 + wn * 64 + nt * 8 + cq * 2;
            float v00 = acc[mt][nt][0], v01 = acc[mt][nt][1];
            float v10 = acc[mt][nt][2], v11 = acc[mt][nt][3];
            if (ROUND_OUT) {
                v00 = cvt_tf32_f(v00); v01 = cvt_tf32_f(v01);
                v10 = cvt_tf32_f(v10); v11 = cvt_tf32_f(v11);
            }
            *reinterpret_cast<float2*>(C + (size_t)row0 * Nn + col0) = make_float2(v00, v01);
            *reinterpret_cast<float2*>(C + (size_t)(row0 + 8) * Nn + col0) = make_float2(v10, v11);
        }
    }
}

// ===========================================================================
// Flash attention via tf32 mma.sync. One block = (b, h), BQ=128, BC=64.
// Inputs (qkv) are PRE-ROUNDED tf32 -> no cvt in staging. Output rounded.
// ===========================================================================
#define APAD 68
#define ASM_K  0
#define ASM_VT (64 * APAD)
#define ASM_P  (2 * 64 * APAD)
#define ATTN_SMEM ((2 * 64 * APAD + 128 * APAD) * 4)   // 69632 B

__global__ __launch_bounds__(256)
void attn_mma(const float* __restrict__ qkv, float* __restrict__ att) {
    extern __shared__ float sm[];
    float* sK  = sm + ASM_K;
    float* sVt = sm + ASM_VT;
    float* sP  = sm + ASM_P;

    int tid = threadIdx.x, lane = tid & 31, wid = tid >> 5;
    int r = lane >> 2, cq = lane & 3;
    int qt = blockIdx.x, h = blockIdx.y, b = blockIdx.z;
    int q0 = qt * 128;

    const float* qbase = qkv + (size_t)b * SEQ * QKVW + h * DH;
    const float* kbase = qbase + INNER;
    const float* vbase = qbase + 2 * INNER;

    #pragma unroll
    for (int i = 0; i < 8; i++) {
        int idx = i * 256 + tid;
        int row = idx >> 4, d4 = (idx & 15) << 2;
        float4 v = *reinterpret_cast<const float4*>(qbase + (size_t)(q0 + row) * QKVW + d4);
        float* p = &sP[row * APAD + d4];
        p[0] = v.x * 0.125f; p[1] = v.y * 0.125f;
        p[2] = v.z * 0.125f; p[3] = v.w * 0.125f;
    }
    __syncthreads();
    uint32_t qf[8][4];
    #pragma unroll
    for (int kt = 0; kt < 8; kt++) {
        const float* p = &sP[(wid * 16 + r) * APAD + kt * 8 + cq];
        qf[kt][0] = __float_as_uint(p[0]);
        qf[kt][1] = __float_as_uint(p[8 * APAD]);
        qf[kt][2] = __float_as_uint(p[4]);
        qf[kt][3] = __float_as_uint(p[8 * APAD + 4]);
    }

    float m0 = -1e30f, m1 = -1e30f, l0 = 0.f, l1 = 0.f;
    float o[8][4];
    #pragma unroll
    for (int nt = 0; nt < 8; nt++)
        #pragma unroll
        for (int j = 0; j < 4; j++) o[nt][j] = 0.f;

    int nchunk = 2 * qt + 2;
    for (int c = 0; c < nchunk; c++) {
        __syncthreads();
        #pragma unroll
        for (int i = 0; i < 4; i++) {
            int idx = i * 256 + tid;
            int row = idx >> 4, d4 = (idx & 15) << 2;
            float4 kv = *reinterpret_cast<const float4*>(kbase + (size_t)(c * 64 + row) * QKVW + d4);
            *reinterpret_cast<float4*>(&sK[row * APAD + d4]) = kv;
            float4 vv = *reinterpret_cast<const float4*>(vbase + (size_t)(c * 64 + row) * QKVW + d4);
            sVt[(d4 + 0) * APAD + row] = vv.x;
            sVt[(d4 + 1) * APAD + row] = vv.y;
            sVt[(d4 + 2) * APAD + row] = vv.z;
            sVt[(d4 + 3) * APAD + row] = vv.w;
        }
        __syncthreads();

        int wrow0 = q0 + wid * 16;
        if (wrow0 + 15 < c * 64) continue;

        float s[8][4];
        #pragma unroll
        for (int nt = 0; nt < 8; nt++)
            #pragma unroll
            for (int j = 0; j < 4; j++) s[nt][j] = 0.f;
        #pragma unroll
        for (int kt = 0; kt < 8; kt++) {
            uint32_t bf[8][2];
            #pragma unroll
            for (int nt = 0; nt < 8; nt++) {
                const float* kp = &sK[(nt * 8 + r) * APAD + kt * 8 + cq];
                bf[nt][0] = __float_as_uint(kp[0]);
                bf[nt][1] = __float_as_uint(kp[4]);
            }
            #pragma unroll
            for (int nt = 0; nt < 8; nt++)
                mma_tf32_16x8x8(s[nt], qf[kt], bf[nt]);
        }

        if (c * 64 + 63 > wrow0) {
            int row_a = wrow0 + r, row_b = wrow0 + r + 8;
            #pragma unroll
            for (int nt = 0; nt < 8; nt++) {
                int col = c * 64 + nt * 8 + 2 * cq;
                if (col     > row_a) s[nt][0] = -1e30f;
                if (col + 1 > row_a) s[nt][1] = -1e30f;
                if (col     > row_b) s[nt][2] = -1e30f;
                if (col + 1 > row_b) s[nt][3] = -1e30f;
            }
        }

        float mt0 = -1e30f, mt1 = -1e30f;
        #pragma unroll
        for (int nt = 0; nt < 8; nt++) {
            mt0 = fmaxf(mt0, fmaxf(s[nt][0], s[nt][1]));
            mt1 = fmaxf(mt1, fmaxf(s[nt][2], s[nt][3]));
        }
        mt0 = fmaxf(mt0, __shfl_xor_sync(0xFFFFFFFFu, mt0, 1));
        mt0 = fmaxf(mt0, __shfl_xor_sync(0xFFFFFFFFu, mt0, 2));
        mt1 = fmaxf(mt1, __shfl_xor_sync(0xFFFFFFFFu, mt1, 1));
        mt1 = fmaxf(mt1, __shfl_xor_sync(0xFFFFFFFFu, mt1, 2));

        float mn0 = fmaxf(m0, mt0), mn1 = fmaxf(m1, mt1);
        float a0 = __expf(m0 - mn0), a1 = __expf(m1 - mn1);
        m0 = mn0; m1 = mn1;
        float rs0 = 0.f, rs1 = 0.f;
        #pragma unroll
        for (int nt = 0; nt < 8; nt++) {
            s[nt][0] = __expf(s[nt][0] - mn0);
            s[nt][1] = __expf(s[nt][1] - mn0);
            s[nt][2] = __expf(s[nt][2] - mn1);
            s[nt][3] = __expf(s[nt][3] - mn1);
            rs0 += s[nt][0] + s[nt][1];
            rs1 += s[nt][2] + s[nt][3];
        }
        rs0 += __shfl_xor_sync(0xFFFFFFFFu, rs0, 1);
        rs0 += __shfl_xor_sync(0xFFFFFFFFu, rs0, 2);
        rs1 += __shfl_xor_sync(0xFFFFFFFFu, rs1, 1);
        rs1 += __shfl_xor_sync(0xFFFFFFFFu, rs1, 2);
        l0 = l0 * a0 + rs0;
        l1 = l1 * a1 + rs1;
        #pragma unroll
        for (int nt = 0; nt < 8; nt++) {
            o[nt][0] *= a0; o[nt][1] *= a0;
            o[nt][2] *= a1; o[nt][3] *= a1;
        }

        float* pr0 = &sP[(wid * 16 + r) * APAD];
        float* pr1 = &sP[(wid * 16 + r + 8) * APAD];
        #pragma unroll
        for (int nt = 0; nt < 8; nt++) {
            int col = nt * 8 + 2 * cq;
            pr0[col]     = cvt_tf32_f(s[nt][0]);
            pr0[col + 1] = cvt_tf32_f(s[nt][1]);
            pr1[col]     = cvt_tf32_f(s[nt][2]);
            pr1[col + 1] = cvt_tf32_f(s[nt][3]);
        }
        __syncwarp();

        #pragma unroll
        for (int kt = 0; kt < 8; kt++) {
            uint32_t pf[4];
            const float* pp = &sP[(wid * 16 + r) * APAD + kt * 8 + cq];
            pf[0] = __float_as_uint(pp[0]);
            pf[1] = __float_as_uint(pp[8 * APAD]);
            pf[2] = __float_as_uint(pp[4]);
            pf[3] = __float_as_uint(pp[8 * APAD + 4]);
            uint32_t bf[8][2];
            #pragma unroll
            for (int nt = 0; nt < 8; nt++) {
                const float* vp = &sVt[(nt * 8 + r) * APAD + kt * 8 + cq];
                bf[nt][0] = __float_as_uint(vp[0]);
                bf[nt][1] = __float_as_uint(vp[4]);
            }
            #pragma unroll
            for (int nt = 0; nt < 8; nt++)
                mma_tf32_16x8x8(o[nt], pf, bf[nt]);
        }
        __syncwarp();
    }

    float inv0 = 1.f / l0, inv1 = 1.f / l1;
    int row_a = q0 + wid * 16 + r, row_b = row_a + 8;
    #pragma unroll
    for (int nt = 0; nt < 8; nt++) {
        int col = h * DH + nt * 8 + 2 * cq;
        *reinterpret_cast<float2*>(att + ((size_t)b * SEQ + row_a) * INNER + col) =
            make_float2(cvt_tf32_f(o[nt][0] * inv0), cvt_tf32_f(o[nt][1] * inv0));
        *reinterpret_cast<float2*>(att + ((size_t)b * SEQ + row_b) * INNER + col) =
            make_float2(cvt_tf32_f(o[nt][2] * inv1), cvt_tf32_f(o[nt][3] * inv1));
    }
}

// ===========================================================================
extern "C" void kernel_launch(void* const* d_in, const int* in_sizes, int n_in,
                              void* d_out, int out_size) {
    const float* x     = (const float*)d_in[0];
    const float* gamma = (const float*)d_in[1];
    const float* beta  = (const float*)d_in[2];
    const float* w_qkv = (const float*)d_in[3];
    const float* w_out = (const float*)d_in[4];
    float* out = (float*)d_out;

    float *xn, *qkv, *att, *wqkvT, *woutT;
    cudaGetSymbolAddress((void**)&xn,    g_xn);
    cudaGetSymbolAddress((void**)&qkv,   g_qkv);
    cudaGetSymbolAddress((void**)&att,   g_att);
    cudaGetSymbolAddress((void**)&wqkvT, g_wqkvT);
    cudaGetSymbolAddress((void**)&woutT, g_woutT);

    cudaFuncSetAttribute(gemm_tf32<true>,  cudaFuncAttributeMaxDynamicSharedMemorySize, GEMM_SMEM);
    cudaFuncSetAttribute(gemm_tf32<false>, cudaFuncAttributeMaxDynamicSharedMemorySize, GEMM_SMEM);
    cudaFuncSetAttribute(attn_mma, cudaFuncAttributeMaxDynamicSharedMemorySize, ATTN_SMEM);

    ln_kernel<<<ROWS, 256>>>(x, gamma, beta, xn);
    transpose_cvt<<<dim3(QKVW / 32, DIMD / 32), dim3(32, 8)>>>(w_qkv, wqkvT, DIMD, QKVW);
    transpose_cvt<<<dim3(DIMD / 32, INNER / 32), dim3(32, 8)>>>(w_out, woutT, INNER, DIMD);
    gemm_tf32<true><<<dim3(QKVW / 256, ROWS / 128), 256, GEMM_SMEM>>>(xn, wqkvT, qkv, ROWS, QKVW, DIMD);
    attn_mma<<<dim3(SEQ / 128, HEADS, BATCH), 256, ATTN_SMEM>>>(qkv, att);
    gemm_tf32<false><<<dim3(DIMD / 256, ROWS / 128), 256, GEMM_SMEM>>>(att, woutT, out, ROWS, DIMD, INNER);
}

// round 7
// speedup vs baseline: 1.1670x; 1.1670x over previous
#include <cuda_runtime.h>
#include <math.h>
#include <cstdint>

#define DIMD   1024
#define HEADS  16
#define DH     64
#define INNER  1024
#define BATCH  4
#define SEQ    2048
#define ROWS   (BATCH*SEQ)      // 8192
#define QKVW   (3*INNER)        // 3072

// Scratch (device globals: allocation-free contract)
__device__ float g_xn   [ROWS*DIMD];        // tf32-rounded LN output
__device__ float g_qkv  [ROWS*QKVW];        // tf32-rounded QKV
__device__ float g_att  [ROWS*INNER];       // tf32-rounded attention output
__device__ float g_wqkvT[QKVW*DIMD];        // tf32-rounded, [N][K]
__device__ float g_woutT[DIMD*INNER];       // tf32-rounded, [N][K]

__device__ __forceinline__ uint32_t cvt_tf32(float f) {
    uint32_t r;
    asm("cvt.rna.tf32.f32 %0, %1;" : "=r"(r) : "f"(f));
    return r;
}
__device__ __forceinline__ float cvt_tf32_f(float f) {
    return __uint_as_float(cvt_tf32(f));
}

__device__ __forceinline__ void mma_tf32_16x8x8(float* d, const uint32_t* a,
                                                const uint32_t* b) {
    asm volatile(
        "mma.sync.aligned.m16n8k8.row.col.f32.tf32.tf32.f32 "
        "{%0,%1,%2,%3}, {%4,%5,%6,%7}, {%8,%9}, {%0,%1,%2,%3};"
        : "+f"(d[0]), "+f"(d[1]), "+f"(d[2]), "+f"(d[3])
        : "r"(a[0]), "r"(a[1]), "r"(a[2]), "r"(a[3]), "r"(b[0]), "r"(b[1]));
}

__device__ __forceinline__ void cp_async16(uint32_t smem_dst, const void* gmem_src) {
    asm volatile("cp.async.cg.shared.global [%0], [%1], 16;" :: "r"(smem_dst), "l"(gmem_src));
}
#define CP_COMMIT() asm volatile("cp.async.commit_group;" ::: "memory")
#define CP_WAIT(n)  asm volatile("cp.async.wait_group %0;" :: "n"(n) : "memory")

// ===========================================================================
// LayerNorm: one block per row, 256 threads, float4; OUTPUT tf32-rounded.
// ===========================================================================
__global__ void ln_kernel(const float* __restrict__ x,
                          const float* __restrict__ gamma,
                          const float* __restrict__ beta,
                          float* __restrict__ out) {
    int row = blockIdx.x;
    int tid = threadIdx.x;
    const float4* xr = reinterpret_cast<const float4*>(x + (size_t)row * DIMD);
    float4 v = xr[tid];
    float s  = v.x + v.y + v.z + v.w;
    float ss = v.x*v.x + v.y*v.y + v.z*v.z + v.w*v.w;
    #pragma unroll
    for (int o = 16; o > 0; o >>= 1) {
        s  += __shfl_xor_sync(0xFFFFFFFFu, s,  o);
        ss += __shfl_xor_sync(0xFFFFFFFFu, ss, o);
    }
    __shared__ float rs[8], rq[8];
    int w = tid >> 5, l = tid & 31;
    if (l == 0) { rs[w] = s; rq[w] = ss; }
    __syncthreads();
    if (w == 0) {
        s  = (l < 8) ? rs[l] : 0.f;
        ss = (l < 8) ? rq[l] : 0.f;
        #pragma unroll
        for (int o = 4; o > 0; o >>= 1) {
            s  += __shfl_xor_sync(0xFFFFFFFFu, s,  o);
            ss += __shfl_xor_sync(0xFFFFFFFFu, ss, o);
        }
        if (l == 0) { rs[0] = s; rq[0] = ss; }
    }
    __syncthreads();
    float mu   = rs[0] * (1.0f / DIMD);
    float var  = rq[0] * (1.0f / DIMD) - mu * mu;
    float rstd = rsqrtf(var + 1e-5f);
    float4 g4 = reinterpret_cast<const float4*>(gamma)[tid];
    float4 b4 = reinterpret_cast<const float4*>(beta)[tid];
    float4 o4;
    o4.x = cvt_tf32_f((v.x - mu) * rstd * g4.x + b4.x);
    o4.y = cvt_tf32_f((v.y - mu) * rstd * g4.y + b4.y);
    o4.z = cvt_tf32_f((v.z - mu) * rstd * g4.z + b4.z);
    o4.w = cvt_tf32_f((v.w - mu) * rstd * g4.w + b4.w);
    reinterpret_cast<float4*>(out + (size_t)row * DIMD)[tid] = o4;
}

// ===========================================================================
// Transpose + round-to-tf32: in [R][Cc] -> out [Cc][R]
// ===========================================================================
__global__ void transpose_cvt(const float* __restrict__ in, float* __restrict__ out,
                              int R, int Cc) {
    __shared__ float t[32][33];
    int c0 = blockIdx.x * 32, r0 = blockIdx.y * 32;
    int x = threadIdx.x, y = threadIdx.y;   // 32 x 8
    #pragma unroll
    for (int i = 0; i < 32; i += 8)
        t[y + i][x] = in[(size_t)(r0 + y + i) * Cc + c0 + x];
    __syncthreads();
    #pragma unroll
    for (int i = 0; i < 32; i += 8) {
        float v = t[x][y + i];
        out[(size_t)(c0 + y + i) * R + r0 + x] = cvt_tf32_f(v);
    }
}

// ===========================================================================
// tf32 mma.sync GEMM, cp.async 2-stage pipeline. (R5 config: best measured)
// C[M,Nn] = A[M,K] @ BT[Nn,K]^T. CTA 128x128, 256 thr, warp tile 64x32.
// ===========================================================================
#define GBK   32
#define GSTR  (GBK + 4)                 // 36 floats row stride
#define GTILE (128 * GSTR)              // floats per tile
#define GEMM_SMEM (4 * GTILE * 4)       // 73728 B

template <bool ROUND_OUT>
__global__ __launch_bounds__(256, 2)
void gemm_tf32(const float* __restrict__ A, const float* __restrict__ BT,
               float* __restrict__ C, int M, int Nn, int K) {
    extern __shared__ float sm[];

    int tid  = threadIdx.x;
    int lane = tid & 31;
    int wid  = tid >> 5;
    int wm   = wid >> 2;
    int wn   = wid & 3;

    const float* Ab = A  + (size_t)blockIdx.y * 128 * K;
    const float* Bb = BT + (size_t)blockIdx.x * 128 * K;

    float acc[4][4][4];
    #pragma unroll
    for (int i = 0; i < 4; i++)
        #pragma unroll
        for (int j = 0; j < 4; j++)
            #pragma unroll
            for (int k = 0; k < 4; k++) acc[i][j][k] = 0.f;

    const int nchunks = K / GBK;
    uint32_t smbase = (uint32_t)__cvta_generic_to_shared(sm);

    auto stage = [&](int c) {
        int buf = c & 1;
        uint32_t sA = smbase + (buf * GTILE) * 4;
        uint32_t sB = smbase + ((2 + buf) * GTILE) * 4;
        const float* Ac = Ab + c * GBK;
        const float* Bc = Bb + c * GBK;
        #pragma unroll
        for (int i = 0; i < 4; i++) {
            int idx = i * 256 + tid;
            int m = idx >> 3, k4 = (idx & 7) << 2;
            cp_async16(sA + (m * GSTR + k4) * 4, Ac + (size_t)m * K + k4);
            cp_async16(sB + (m * GSTR + k4) * 4, Bc + (size_t)m * K + k4);
        }
    };

    stage(0);
    CP_COMMIT();

    int r  = lane >> 2;
    int cq = lane & 3;

    for (int c = 0; c < nchunks; c++) {
        if (c + 1 < nchunks) {
            stage(c + 1);
            CP_COMMIT();
            CP_WAIT(1);
        } else {
            CP_WAIT(0);
        }
        __syncthreads();

        const float* As = sm + (c & 1) * GTILE;
        const float* Bs = sm + (2 + (c & 1)) * GTILE;

        #pragma unroll
        for (int ks = 0; ks < 4; ks++) {
            uint32_t a[4][4], b[4][2];
            #pragma unroll
            for (int mt = 0; mt < 4; mt++) {
                const float* ap = &As[(wm * 64 + mt * 16 + r) * GSTR + ks * 8 + cq];
                a[mt][0] = __float_as_uint(ap[0]);
                a[mt][1] = __float_as_uint(ap[8 * GSTR]);
                a[mt][2] = __float_as_uint(ap[4]);
                a[mt][3] = __float_as_uint(ap[8 * GSTR + 4]);
            }
            #pragma unroll
            for (int nt = 0; nt < 4; nt++) {
                const float* bp = &Bs[(wn * 32 + nt * 8 + r) * GSTR + ks * 8 + cq];
                b[nt][0] = __float_as_uint(bp[0]);
                b[nt][1] = __float_as_uint(bp[4]);
            }
            #pragma unroll
            for (int mt = 0; mt < 4; mt++)
                #pragma unroll
                for (int nt = 0; nt < 4; nt++)
                    mma_tf32_16x8x8(acc[mt][nt], a[mt], b[nt]);
        }
        __syncthreads();
    }

    #pragma unroll
    for (int mt = 0; mt < 4; mt++) {
        int row0 = blockIdx.y * 128 + wm * 64 + mt * 16 + r;
        #pragma unroll
        for (int nt = 0; nt < 4; nt++) {
            int col0 = blockIdx.x * 128 + wn * 32 + nt * 8 + cq * 2;
            float v00 = acc[mt][nt][0], v01 = acc[mt][nt][1];
            float v10 = acc[mt][nt][2], v11 = acc[mt][nt][3];
            if (ROUND_OUT) {
                v00 = cvt_tf32_f(v00); v01 = cvt_tf32_f(v01);
                v10 = cvt_tf32_f(v10); v11 = cvt_tf32_f(v11);
            }
            *reinterpret_cast<float2*>(C + (size_t)row0 * Nn + col0) = make_float2(v00, v01);
            *reinterpret_cast<float2*>(C + (size_t)(row0 + 8) * Nn + col0) = make_float2(v10, v11);
        }
    }
}

// ===========================================================================
// Flash attention, tf32 mma.sync, cp.async double-buffered K/V.
// One block = (b, h), BQ=128, BC=64, 8 warps x 16 q-rows.
// K stored [kv][d] stride 68 (read as B with n=kv, k=d);
// V stored [kv][d] stride 72 (read as B with n=d, k=kv — no transpose).
// ===========================================================================
#define KSTR 68
#define VSTR 72
#define KTILE (64 * KSTR)                 // 4352 floats
#define VTILE (64 * VSTR)                 // 4608 floats
#define ASM_SP (2 * KTILE + 2 * VTILE)    // 17920 floats
#define SPSTR 68
#define ATTN_SMEM ((ASM_SP + 128 * SPSTR) * 4)   // 106496 B

__global__ __launch_bounds__(256)
void attn_mma(const float* __restrict__ qkv, float* __restrict__ att) {
    extern __shared__ float sm[];
    float* sP = sm + ASM_SP;

    int tid = threadIdx.x, lane = tid & 31, wid = tid >> 5;
    int r = lane >> 2, cq = lane & 3;
    int qt = gridDim.x - 1 - blockIdx.x;     // longest tiles first
    int h = blockIdx.y, b = blockIdx.z;
    int q0 = qt * 128;

    const float* qbase = qkv + (size_t)b * SEQ * QKVW + h * DH;
    const float* kbase = qbase + INNER;
    const float* vbase = qbase + 2 * INNER;

    uint32_t smb = (uint32_t)__cvta_generic_to_shared(sm);
    uint32_t spb = smb + ASM_SP * 4;

    const int nchunk = 2 * qt + 2;

    auto stage = [&](int c) {
        int buf = c & 1;
        uint32_t sK = smb + (buf * KTILE) * 4;
        uint32_t sV = smb + (2 * KTILE + buf * VTILE) * 4;
        const float* kc = kbase + (size_t)c * 64 * QKVW;
        const float* vc = vbase + (size_t)c * 64 * QKVW;
        #pragma unroll
        for (int i = 0; i < 4; i++) {
            int idx = i * 256 + tid;
            int row = idx >> 4, d4 = (idx & 15) << 2;
            cp_async16(sK + (row * KSTR + d4) * 4, kc + (size_t)row * QKVW + d4);
            cp_async16(sV + (row * VSTR + d4) * 4, vc + (size_t)row * QKVW + d4);
        }
    };

    // group 0: Q tile + chunk 0 K/V
    #pragma unroll
    for (int i = 0; i < 8; i++) {
        int idx = i * 256 + tid;
        int row = idx >> 4, d4 = (idx & 15) << 2;
        cp_async16(spb + (row * SPSTR + d4) * 4, qbase + (size_t)(q0 + row) * QKVW + d4);
    }
    stage(0);
    CP_COMMIT();

    uint32_t qf[8][4];
    float m0 = -1e30f, m1 = -1e30f, l0 = 0.f, l1 = 0.f;
    float o[8][4];
    #pragma unroll
    for (int nt = 0; nt < 8; nt++)
        #pragma unroll
        for (int j = 0; j < 4; j++) o[nt][j] = 0.f;

    for (int c = 0; c < nchunk; c++) {
        if (c + 1 < nchunk) {
            stage(c + 1);
            CP_COMMIT();
            CP_WAIT(1);
        } else {
            CP_WAIT(0);
        }
        __syncthreads();

        if (c == 0) {
            // build Q fragments (x0.125 exact; inputs pre-rounded tf32)
            #pragma unroll
            for (int kt = 0; kt < 8; kt++) {
                const float* p = &sP[(wid * 16 + r) * SPSTR + kt * 8 + cq];
                qf[kt][0] = __float_as_uint(p[0] * 0.125f);
                qf[kt][1] = __float_as_uint(p[8 * SPSTR] * 0.125f);
                qf[kt][2] = __float_as_uint(p[4] * 0.125f);
                qf[kt][3] = __float_as_uint(p[8 * SPSTR + 4] * 0.125f);
            }
            __syncthreads();   // all reads of Q from sP done before P overwrites
        }

        const float* sK = sm + (c & 1) * KTILE;
        const float* sV = sm + 2 * KTILE + (c & 1) * VTILE;

        int wrow0 = q0 + wid * 16;
        if (wrow0 + 15 >= c * 64) {
            // ---- S = Q @ K^T
            float s[8][4];
            #pragma unroll
            for (int nt = 0; nt < 8; nt++)
                #pragma unroll
                for (int j = 0; j < 4; j++) s[nt][j] = 0.f;
            #pragma unroll
            for (int kt = 0; kt < 8; kt++) {
                uint32_t bf[8][2];
                #pragma unroll
                for (int nt = 0; nt < 8; nt++) {
                    const float* kp = &sK[(nt * 8 + r) * KSTR + kt * 8 + cq];
                    bf[nt][0] = __float_as_uint(kp[0]);
                    bf[nt][1] = __float_as_uint(kp[4]);
                }
                #pragma unroll
                for (int nt = 0; nt < 8; nt++)
                    mma_tf32_16x8x8(s[nt], qf[kt], bf[nt]);
            }

            // ---- causal mask
            if (c * 64 + 63 > wrow0) {
                int row_a = wrow0 + r, row_b = wrow0 + r + 8;
                #pragma unroll
                for (int nt = 0; nt < 8; nt++) {
                    int col = c * 64 + nt * 8 + 2 * cq;
                    if (col     > row_a) s[nt][0] = -1e30f;
                    if (col + 1 > row_a) s[nt][1] = -1e30f;
                    if (col     > row_b) s[nt][2] = -1e30f;
                    if (col + 1 > row_b) s[nt][3] = -1e30f;
                }
            }

            // ---- online softmax
            float mt0 = -1e30f, mt1 = -1e30f;
            #pragma unroll
            for (int nt = 0; nt < 8; nt++) {
                mt0 = fmaxf(mt0, fmaxf(s[nt][0], s[nt][1]));
                mt1 = fmaxf(mt1, fmaxf(s[nt][2], s[nt][3]));
            }
            mt0 = fmaxf(mt0, __shfl_xor_sync(0xFFFFFFFFu, mt0, 1));
            mt0 = fmaxf(mt0, __shfl_xor_sync(0xFFFFFFFFu, mt0, 2));
            mt1 = fmaxf(mt1, __shfl_xor_sync(0xFFFFFFFFu, mt1, 1));
            mt1 = fmaxf(mt1, __shfl_xor_sync(0xFFFFFFFFu, mt1, 2));

            float mn0 = fmaxf(m0, mt0), mn1 = fmaxf(m1, mt1);
            float a0 = __expf(m0 - mn0), a1 = __expf(m1 - mn1);
            m0 = mn0; m1 = mn1;
            float rs0 = 0.f, rs1 = 0.f;
            #pragma unroll
            for (int nt = 0; nt < 8; nt++) {
                s[nt][0] = __expf(s[nt][0] - mn0);
                s[nt][1] = __expf(s[nt][1] - mn0);
                s[nt][2] = __expf(s[nt][2] - mn1);
                s[nt][3] = __expf(s[nt][3] - mn1);
                rs0 += s[nt][0] + s[nt][1];
                rs1 += s[nt][2] + s[nt][3];
            }
            rs0 += __shfl_xor_sync(0xFFFFFFFFu, rs0, 1);
            rs0 += __shfl_xor_sync(0xFFFFFFFFu, rs0, 2);
            rs1 += __shfl_xor_sync(0xFFFFFFFFu, rs1, 1);
            rs1 += __shfl_xor_sync(0xFFFFFFFFu, rs1, 2);
            l0 = l0 * a0 + rs0;
            l1 = l1 * a1 + rs1;
            #pragma unroll
            for (int nt = 0; nt < 8; nt++) {
                o[nt][0] *= a0; o[nt][1] *= a0;
                o[nt][2] *= a1; o[nt][3] *= a1;
            }

            // ---- P -> warp-private smem (tf32)
            float* pr0 = &sP[(wid * 16 + r) * SPSTR];
            float* pr1 = &sP[(wid * 16 + r + 8) * SPSTR];
            #pragma unroll
            for (int nt = 0; nt < 8; nt++) {
                int col = nt * 8 + 2 * cq;
                pr0[col]     = cvt_tf32_f(s[nt][0]);
                pr0[col + 1] = cvt_tf32_f(s[nt][1]);
                pr1[col]     = cvt_tf32_f(s[nt][2]);
                pr1[col + 1] = cvt_tf32_f(s[nt][3]);
            }
            __syncwarp();

            // ---- O += P @ V   (V natural [kv][d]: b_j = V[kv=kt*8+cq+4j][d=nt*8+r])
            #pragma unroll
            for (int kt = 0; kt < 8; kt++) {
                uint32_t pf[4];
                const float* pp = &sP[(wid * 16 + r) * SPSTR + kt * 8 + cq];
                pf[0] = __float_as_uint(pp[0]);
                pf[1] = __float_as_uint(pp[8 * SPSTR]);
                pf[2] = __float_as_uint(pp[4]);
                pf[3] = __float_as_uint(pp[8 * SPSTR + 4]);
                uint32_t bf[8][2];
                #pragma unroll
                for (int nt = 0; nt < 8; nt++) {
                    bf[nt][0] = __float_as_uint(sV[(kt * 8 + cq) * VSTR + nt * 8 + r]);
                    bf[nt][1] = __float_as_uint(sV[(kt * 8 + cq + 4) * VSTR + nt * 8 + r]);
                }
                #pragma unroll
                for (int nt = 0; nt < 8; nt++)
                    mma_tf32_16x8x8(o[nt], pf, bf[nt]);
            }
        }
        __syncthreads();
    }

    float inv0 = 1.f / l0, inv1 = 1.f / l1;
    int row_a = q0 + wid * 16 + r, row_b = row_a + 8;
    #pragma unroll
    for (int nt = 0; nt < 8; nt++) {
        int col = h * DH + nt * 8 + 2 * cq;
        *reinterpret_cast<float2*>(att + ((size_t)b * SEQ + row_a) * INNER + col) =
            make_float2(cvt_tf32_f(o[nt][0] * inv0), cvt_tf32_f(o[nt][1] * inv0));
        *reinterpret_cast<float2*>(att + ((size_t)b * SEQ + row_b) * INNER + col) =
            make_float2(cvt_tf32_f(o[nt][2] * inv1), cvt_tf32_f(o[nt][3] * inv1));
    }
}

// ===========================================================================
extern "C" void kernel_launch(void* const* d_in, const int* in_sizes, int n_in,
                              void* d_out, int out_size) {
    const float* x     = (const float*)d_in[0];
    const float* gamma = (const float*)d_in[1];
    const float* beta  = (const float*)d_in[2];
    const float* w_qkv = (const float*)d_in[3];
    const float* w_out = (const float*)d_in[4];
    float* out = (float*)d_out;

    float *xn, *qkv, *att, *wqkvT, *woutT;
    cudaGetSymbolAddress((void**)&xn,    g_xn);
    cudaGetSymbolAddress((void**)&qkv,   g_qkv);
    cudaGetSymbolAddress((void**)&att,   g_att);
    cudaGetSymbolAddress((void**)&wqkvT, g_wqkvT);
    cudaGetSymbolAddress((void**)&woutT, g_woutT);

    cudaFuncSetAttribute(gemm_tf32<true>,  cudaFuncAttributeMaxDynamicSharedMemorySize, GEMM_SMEM);
    cudaFuncSetAttribute(gemm_tf32<false>, cudaFuncAttributeMaxDynamicSharedMemorySize, GEMM_SMEM);
    cudaFuncSetAttribute(attn_mma, cudaFuncAttributeMaxDynamicSharedMemorySize, ATTN_SMEM);

    ln_kernel<<<ROWS, 256>>>(x, gamma, beta, xn);
    transpose_cvt<<<dim3(QKVW / 32, DIMD / 32), dim3(32, 8)>>>(w_qkv, wqkvT, DIMD, QKVW);
    transpose_cvt<<<dim3(DIMD / 32, INNER / 32), dim3(32, 8)>>>(w_out, woutT, INNER, DIMD);
    gemm_tf32<true><<<dim3(QKVW / 128, ROWS / 128), 256, GEMM_SMEM>>>(xn, wqkvT, qkv, ROWS, QKVW, DIMD);
    attn_mma<<<dim3(SEQ / 128, HEADS, BATCH), 256, ATTN_SMEM>>>(qkv, att);
    gemm_tf32<false><<<dim3(DIMD / 128, ROWS / 128), 256, GEMM_SMEM>>>(att, woutT, out, ROWS, DIMD, INNER);
}

// round 8
// speedup vs baseline: 1.2601x; 1.0798x over previous
#include <cuda_runtime.h>
#include <math.h>
#include <cstdint>

#define DIMD   1024
#define HEADS  16
#define DH     64
#define INNER  1024
#define BATCH  4
#define SEQ    2048
#define ROWS   (BATCH*SEQ)      // 8192
#define QKVW   (3*INNER)        // 3072

// Scratch (device globals: allocation-free contract)
__device__ float g_xn   [ROWS*DIMD];        // tf32, K-interleaved columns
__device__ float g_qkv  [ROWS*QKVW];        // tf32; q,k sections d-interleaved
__device__ float g_att  [ROWS*INNER];       // tf32, K-interleaved columns
__device__ float g_wqkvT[QKVW*DIMD];        // tf32, [N][K], K interleaved, q/k rows interleaved
__device__ float g_woutT[DIMD*INNER];       // tf32, [N][K], K interleaved

// k-interleave permutation within each 8-group: true c -> stored (c<4 ? 2c : 2c-7)
__host__ __device__ __forceinline__ int f2i(int x) {
    int c = x & 7;
    return (x & ~7) | ((c < 4) ? (2 * c) : (2 * c - 7));
}

__device__ __forceinline__ uint32_t cvt_tf32(float f) {
    uint32_t r;
    asm("cvt.rna.tf32.f32 %0, %1;" : "=r"(r) : "f"(f));
    return r;
}
__device__ __forceinline__ float cvt_tf32_f(float f) {
    return __uint_as_float(cvt_tf32(f));
}

__device__ __forceinline__ void mma_tf32_16x8x8(float* d, const uint32_t* a,
                                                const uint32_t* b) {
    asm volatile(
        "mma.sync.aligned.m16n8k8.row.col.f32.tf32.tf32.f32 "
        "{%0,%1,%2,%3}, {%4,%5,%6,%7}, {%8,%9}, {%0,%1,%2,%3};"
        : "+f"(d[0]), "+f"(d[1]), "+f"(d[2]), "+f"(d[3])
        : "r"(a[0]), "r"(a[1]), "r"(a[2]), "r"(a[3]), "r"(b[0]), "r"(b[1]));
}

__device__ __forceinline__ void cp_async16(uint32_t smem_dst, const void* gmem_src) {
    asm volatile("cp.async.cg.shared.global [%0], [%1], 16;" :: "r"(smem_dst), "l"(gmem_src));
}
#define CP_COMMIT() asm volatile("cp.async.commit_group;" ::: "memory")
#define CP_WAIT(n)  asm volatile("cp.async.wait_group %0;" :: "n"(n) : "memory")

// ===========================================================================
// LayerNorm: one block per row, 256 threads; OUTPUT tf32, K-interleaved.
// ===========================================================================
__global__ void ln_kernel(const float* __restrict__ x,
                          const float* __restrict__ gamma,
                          const float* __restrict__ beta,
                          float* __restrict__ out) {
    __shared__ float srow[DIMD];
    int row = blockIdx.x;
    int tid = threadIdx.x;
    const float4* xr = reinterpret_cast<const float4*>(x + (size_t)row * DIMD);
    float4 v = xr[tid];
    float s  = v.x + v.y + v.z + v.w;
    float ss = v.x*v.x + v.y*v.y + v.z*v.z + v.w*v.w;
    #pragma unroll
    for (int o = 16; o > 0; o >>= 1) {
        s  += __shfl_xor_sync(0xFFFFFFFFu, s,  o);
        ss += __shfl_xor_sync(0xFFFFFFFFu, ss, o);
    }
    __shared__ float rs[8], rq[8];
    int w = tid >> 5, l = tid & 31;
    if (l == 0) { rs[w] = s; rq[w] = ss; }
    __syncthreads();
    if (w == 0) {
        s  = (l < 8) ? rs[l] : 0.f;
        ss = (l < 8) ? rq[l] : 0.f;
        #pragma unroll
        for (int o = 4; o > 0; o >>= 1) {
            s  += __shfl_xor_sync(0xFFFFFFFFu, s,  o);
            ss += __shfl_xor_sync(0xFFFFFFFFu, ss, o);
        }
        if (l == 0) { rs[0] = s; rq[0] = ss; }
    }
    __syncthreads();
    float mu   = rs[0] * (1.0f / DIMD);
    float var  = rq[0] * (1.0f / DIMD) - mu * mu;
    float rstd = rsqrtf(var + 1e-5f);
    float4 g4 = reinterpret_cast<const float4*>(gamma)[tid];
    float4 b4 = reinterpret_cast<const float4*>(beta)[tid];
    srow[tid*4+0] = cvt_tf32_f((v.x - mu) * rstd * g4.x + b4.x);
    srow[tid*4+1] = cvt_tf32_f((v.y - mu) * rstd * g4.y + b4.y);
    srow[tid*4+2] = cvt_tf32_f((v.z - mu) * rstd * g4.z + b4.z);
    srow[tid*4+3] = cvt_tf32_f((v.w - mu) * rstd * g4.w + b4.w);
    __syncthreads();
    // stored[8g+s] = true[8g+t(s)], t = {0,4,1,5,2,6,3,7}
    int g8 = (tid >> 1) * 8;
    float4 w4;
    if (tid & 1) { w4 = make_float4(srow[g8+2], srow[g8+6], srow[g8+3], srow[g8+7]); }
    else         { w4 = make_float4(srow[g8+0], srow[g8+4], srow[g8+1], srow[g8+5]); }
    reinterpret_cast<float4*>(out + (size_t)row * DIMD)[tid] = w4;
}

// ===========================================================================
// Transpose + round-to-tf32 + permutations: in [R][Cc] -> out [Cc][R].
// Columns (K dim) always f2-interleaved; rows < rowlim also f2-interleaved
// (used to d-interleave the q/k sections of wqkvT for attention).
// ===========================================================================
__global__ void transpose_cvt(const float* __restrict__ in, float* __restrict__ out,
                              int R, int Cc, int rowlim) {
    __shared__ float t[32][33];
    int c0 = blockIdx.x * 32, r0 = blockIdx.y * 32;
    int x = threadIdx.x, y = threadIdx.y;   // 32 x 8
    #pragma unroll
    for (int i = 0; i < 32; i += 8)
        t[y + i][x] = in[(size_t)(r0 + y + i) * Cc + c0 + x];
    __syncthreads();
    int colp = r0 + f2i(x);
    #pragma unroll
    for (int i = 0; i < 32; i += 8) {
        int rown = c0 + y + i;
        int rowp = (rown < rowlim) ? f2i(rown) : rown;
        out[(size_t)rowp * R + colp] = cvt_tf32_f(t[x][y + i]);
    }
}

// ===========================================================================
// tf32 mma.sync GEMM, cp.async 2-stage, K-interleaved operands -> LDS.64 frags.
// C[M,Nn] = A[M,K] @ BT[Nn,K]^T. CTA 128x128, 256 thr, warp tile 64x32.
// ===========================================================================
#define GBK   32
#define GSTR  40                        // stride mod 32 == 8 -> conflict-free LDS.64
#define GTILE (128 * GSTR)
#define GEMM_SMEM (4 * GTILE * 4)       // 81920 B

template <bool ROUND_OUT>
__global__ __launch_bounds__(256, 2)
void gemm_tf32(const float* __restrict__ A, const float* __restrict__ BT,
               float* __restrict__ C, int M, int Nn, int K) {
    extern __shared__ float sm[];

    int tid  = threadIdx.x;
    int lane = tid & 31;
    int wid  = tid >> 5;
    int wm   = wid >> 2;
    int wn   = wid & 3;

    const float* Ab = A  + (size_t)blockIdx.y * 128 * K;
    const float* Bb = BT + (size_t)blockIdx.x * 128 * K;

    float acc[4][4][4];
    #pragma unroll
    for (int i = 0; i < 4; i++)
        #pragma unroll
        for (int j = 0; j < 4; j++)
            #pragma unroll
            for (int k = 0; k < 4; k++) acc[i][j][k] = 0.f;

    const int nchunks = K / GBK;
    uint32_t smbase = (uint32_t)__cvta_generic_to_shared(sm);

    auto stage = [&](int c) {
        int buf = c & 1;
        uint32_t sA = smbase + (buf * GTILE) * 4;
        uint32_t sB = smbase + ((2 + buf) * GTILE) * 4;
        const float* Ac = Ab + c * GBK;
        const float* Bc = Bb + c * GBK;
        #pragma unroll
        for (int i = 0; i < 4; i++) {
            int idx = i * 256 + tid;
            int m = idx >> 3, k4 = (idx & 7) << 2;
            cp_async16(sA + (m * GSTR + k4) * 4, Ac + (size_t)m * K + k4);
            cp_async16(sB + (m * GSTR + k4) * 4, Bc + (size_t)m * K + k4);
        }
    };

    stage(0);
    CP_COMMIT();

    int r  = lane >> 2;
    int cq = lane & 3;

    for (int c = 0; c < nchunks; c++) {
        if (c + 1 < nchunks) {
            stage(c + 1);
            CP_COMMIT();
            CP_WAIT(1);
        } else {
            CP_WAIT(0);
        }
        __syncthreads();

        const float* As = sm + (c & 1) * GTILE;
        const float* Bs = sm + (2 + (c & 1)) * GTILE;

        #pragma unroll
        for (int ks = 0; ks < 4; ks++) {
            uint32_t a[4][4], b[4][2];
            #pragma unroll
            for (int mt = 0; mt < 4; mt++) {
                int m0 = wm * 64 + mt * 16 + r;
                float2 alo = *reinterpret_cast<const float2*>(&As[m0 * GSTR + ks * 8 + 2 * cq]);
                float2 ahi = *reinterpret_cast<const float2*>(&As[(m0 + 8) * GSTR + ks * 8 + 2 * cq]);
                a[mt][0] = __float_as_uint(alo.x);
                a[mt][1] = __float_as_uint(ahi.x);
                a[mt][2] = __float_as_uint(alo.y);
                a[mt][3] = __float_as_uint(ahi.y);
            }
            #pragma unroll
            for (int nt = 0; nt < 4; nt++) {
                int n0 = wn * 32 + nt * 8 + r;
                float2 bb = *reinterpret_cast<const float2*>(&Bs[n0 * GSTR + ks * 8 + 2 * cq]);
                b[nt][0] = __float_as_uint(bb.x);
                b[nt][1] = __float_as_uint(bb.y);
            }
            #pragma unroll
            for (int mt = 0; mt < 4; mt++)
                #pragma unroll
                for (int nt = 0; nt < 4; nt++)
                    mma_tf32_16x8x8(acc[mt][nt], a[mt], b[nt]);
        }
        __syncthreads();
    }

    #pragma unroll
    for (int mt = 0; mt < 4; mt++) {
        int row0 = blockIdx.y * 128 + wm * 64 + mt * 16 + r;
        #pragma unroll
        for (int nt = 0; nt < 4; nt++) {
            int col0 = blockIdx.x * 128 + wn * 32 + nt * 8 + cq * 2;
            float v00 = acc[mt][nt][0], v01 = acc[mt][nt][1];
            float v10 = acc[mt][nt][2], v11 = acc[mt][nt][3];
            if (ROUND_OUT) {
                v00 = cvt_tf32_f(v00); v01 = cvt_tf32_f(v01);
                v10 = cvt_tf32_f(v10); v11 = cvt_tf32_f(v11);
            }
            *reinterpret_cast<float2*>(C + (size_t)row0 * Nn + col0) = make_float2(v00, v01);
            *reinterpret_cast<float2*>(C + (size_t)(row0 + 8) * Nn + col0) = make_float2(v10, v11);
        }
    }
}

// ===========================================================================
// Flash attention, tf32 mma.sync, cp.async double-buffered K/V.
// q,k sections of qkv are d-interleaved -> LDS.64 K fragments.
// Output att written K-interleaved (for GEMM2).
// ===========================================================================
#define KSTR 72
#define VSTR 72
#define SPSTR 72
#define KTILE (64 * KSTR)
#define VTILE (64 * VSTR)
#define ASM_SP (2 * KTILE + 2 * VTILE)
#define ATTN_SMEM ((ASM_SP + 128 * SPSTR) * 4)   // 110592 B

__global__ __launch_bounds__(256)
void attn_mma(const float* __restrict__ qkv, float* __restrict__ att) {
    extern __shared__ float sm[];
    float* sP = sm + ASM_SP;

    int tid = threadIdx.x, lane = tid & 31, wid = tid >> 5;
    int r = lane >> 2, cq = lane & 3;
    int qt = gridDim.x - 1 - blockIdx.x;     // longest tiles first
    int h = blockIdx.y, b = blockIdx.z;
    int q0 = qt * 128;

    const float* qbase = qkv + (size_t)b * SEQ * QKVW + h * DH;
    const float* kbase = qbase + INNER;
    const float* vbase = qbase + 2 * INNER;

    uint32_t smb = (uint32_t)__cvta_generic_to_shared(sm);
    uint32_t spb = smb + ASM_SP * 4;

    const int nchunk = 2 * qt + 2;

    auto stage = [&](int c) {
        int buf = c & 1;
        uint32_t sK = smb + (buf * KTILE) * 4;
        uint32_t sV = smb + (2 * KTILE + buf * VTILE) * 4;
        const float* kc = kbase + (size_t)c * 64 * QKVW;
        const float* vc = vbase + (size_t)c * 64 * QKVW;
        #pragma unroll
        for (int i = 0; i < 4; i++) {
            int idx = i * 256 + tid;
            int row = idx >> 4, d4 = (idx & 15) << 2;
            cp_async16(sK + (row * KSTR + d4) * 4, kc + (size_t)row * QKVW + d4);
            cp_async16(sV + (row * VSTR + d4) * 4, vc + (size_t)row * QKVW + d4);
        }
    };

    #pragma unroll
    for (int i = 0; i < 8; i++) {
        int idx = i * 256 + tid;
        int row = idx >> 4, d4 = (idx & 15) << 2;
        cp_async16(spb + (row * SPSTR + d4) * 4, qbase + (size_t)(q0 + row) * QKVW + d4);
    }
    stage(0);
    CP_COMMIT();

    uint32_t qf[8][4];
    float m0 = -1e30f, m1 = -1e30f, l0 = 0.f, l1 = 0.f;
    float o[8][4];
    #pragma unroll
    for (int nt = 0; nt < 8; nt++)
        #pragma unroll
        for (int j = 0; j < 4; j++) o[nt][j] = 0.f;

    for (int c = 0; c < nchunk; c++) {
        if (c + 1 < nchunk) {
            stage(c + 1);
            CP_COMMIT();
            CP_WAIT(1);
        } else {
            CP_WAIT(0);
        }
        __syncthreads();

        if (c == 0) {
            // Q fragments (d-interleaved storage -> float2 pairs), x0.125 exact
            #pragma unroll
            for (int kt = 0; kt < 8; kt++) {
                const float* p = &sP[(wid * 16 + r) * SPSTR + kt * 8 + 2 * cq];
                float2 qlo = *reinterpret_cast<const float2*>(p);
                float2 qhi = *reinterpret_cast<const float2*>(p + 8 * SPSTR);
                qf[kt][0] = __float_as_uint(qlo.x * 0.125f);
                qf[kt][1] = __float_as_uint(qhi.x * 0.125f);
                qf[kt][2] = __float_as_uint(qlo.y * 0.125f);
                qf[kt][3] = __float_as_uint(qhi.y * 0.125f);
            }
            __syncthreads();
        }

        const float* sK = sm + (c & 1) * KTILE;
        const float* sV = sm + 2 * KTILE + (c & 1) * VTILE;

        int wrow0 = q0 + wid * 16;
        if (wrow0 + 15 >= c * 64) {
            // ---- S = Q @ K^T (K d-interleaved -> LDS.64 b-frags)
            float s[8][4];
            #pragma unroll
            for (int nt = 0; nt < 8; nt++)
                #pragma unroll
                for (int j = 0; j < 4; j++) s[nt][j] = 0.f;
            #pragma unroll
            for (int kt = 0; kt < 8; kt++) {
                uint32_t bf[8][2];
                #pragma unroll
                for (int nt = 0; nt < 8; nt++) {
                    float2 kk = *reinterpret_cast<const float2*>(
                        &sK[(nt * 8 + r) * KSTR + kt * 8 + 2 * cq]);
                    bf[nt][0] = __float_as_uint(kk.x);
                    bf[nt][1] = __float_as_uint(kk.y);
                }
                #pragma unroll
                for (int nt = 0; nt < 8; nt++)
                    mma_tf32_16x8x8(s[nt], qf[kt], bf[nt]);
            }

            // ---- causal mask
            if (c * 64 + 63 > wrow0) {
                int row_a = wrow0 + r, row_b = wrow0 + r + 8;
                #pragma unroll
                for (int nt = 0; nt < 8; nt++) {
                    int col = c * 64 + nt * 8 + 2 * cq;
                    if (col     > row_a) s[nt][0] = -1e30f;
                    if (col + 1 > row_a) s[nt][1] = -1e30f;
                    if (col     > row_b) s[nt][2] = -1e30f;
                    if (col + 1 > row_b) s[nt][3] = -1e30f;
                }
            }

            // ---- online softmax
            float mt0 = -1e30f, mt1 = -1e30f;
            #pragma unroll
            for (int nt = 0; nt < 8; nt++) {
                mt0 = fmaxf(mt0, fmaxf(s[nt][0], s[nt][1]));
                mt1 = fmaxf(mt1, fmaxf(s[nt][2], s[nt][3]));
            }
            mt0 = fmaxf(mt0, __shfl_xor_sync(0xFFFFFFFFu, mt0, 1));
            mt0 = fmaxf(mt0, __shfl_xor_sync(0xFFFFFFFFu, mt0, 2));
            mt1 = fmaxf(mt1, __shfl_xor_sync(0xFFFFFFFFu, mt1, 1));
            mt1 = fmaxf(mt1, __shfl_xor_sync(0xFFFFFFFFu, mt1, 2));

            float mn0 = fmaxf(m0, mt0), mn1 = fmaxf(m1, mt1);
            float a0 = __expf(m0 - mn0), a1 = __expf(m1 - mn1);
            m0 = mn0; m1 = mn1;
            float rs0 = 0.f, rs1 = 0.f;
            #pragma unroll
            for (int nt = 0; nt < 8; nt++) {
                s[nt][0] = __expf(s[nt][0] - mn0);
                s[nt][1] = __expf(s[nt][1] - mn0);
                s[nt][2] = __expf(s[nt][2] - mn1);
                s[nt][3] = __expf(s[nt][3] - mn1);
                rs0 += s[nt][0] + s[nt][1];
                rs1 += s[nt][2] + s[nt][3];
            }
            rs0 += __shfl_xor_sync(0xFFFFFFFFu, rs0, 1);
            rs0 += __shfl_xor_sync(0xFFFFFFFFu, rs0, 2);
            rs1 += __shfl_xor_sync(0xFFFFFFFFu, rs1, 1);
            rs1 += __shfl_xor_sync(0xFFFFFFFFu, rs1, 2);
            l0 = l0 * a0 + rs0;
            l1 = l1 * a1 + rs1;
            #pragma unroll
            for (int nt = 0; nt < 8; nt++) {
                o[nt][0] *= a0; o[nt][1] *= a0;
                o[nt][2] *= a1; o[nt][3] *= a1;
            }

            // ---- P -> warp-private smem (tf32, STS.64)
            float* pr0 = &sP[(wid * 16 + r) * SPSTR];
            float* pr1 = &sP[(wid * 16 + r + 8) * SPSTR];
            #pragma unroll
            for (int nt = 0; nt < 8; nt++) {
                int col = nt * 8 + 2 * cq;
                *reinterpret_cast<float2*>(&pr0[col]) =
                    make_float2(cvt_tf32_f(s[nt][0]), cvt_tf32_f(s[nt][1]));
                *reinterpret_cast<float2*>(&pr1[col]) =
                    make_float2(cvt_tf32_f(s[nt][2]), cvt_tf32_f(s[nt][3]));
            }
            __syncwarp();

            // ---- O += P @ V  (V natural [kv][d])
            #pragma unroll
            for (int kt = 0; kt < 8; kt++) {
                uint32_t pf[4];
                const float* pp = &sP[(wid * 16 + r) * SPSTR + kt * 8 + cq];
                pf[0] = __float_as_uint(pp[0]);
                pf[1] = __float_as_uint(pp[8 * SPSTR]);
                pf[2] = __float_as_uint(pp[4]);
                pf[3] = __float_as_uint(pp[8 * SPSTR + 4]);
                uint32_t bf[8][2];
                #pragma unroll
                for (int nt = 0; nt < 8; nt++) {
                    bf[nt][0] = __float_as_uint(sV[(kt * 8 + cq) * VSTR + nt * 8 + r]);
                    bf[nt][1] = __float_as_uint(sV[(kt * 8 + cq + 4) * VSTR + nt * 8 + r]);
                }
                #pragma unroll
                for (int nt = 0; nt < 8; nt++)
                    mma_tf32_16x8x8(o[nt], pf, bf[nt]);
            }
        }
        __syncthreads();
    }

    // ---- epilogue: write att with K-interleaved columns (for GEMM2)
    float inv0 = 1.f / l0, inv1 = 1.f / l1;
    int row_a = q0 + wid * 16 + r, row_b = row_a + 8;
    int s0off = (cq < 2) ? 4 * cq : 4 * cq - 7;       // f2(2cq)
    int s1off = (cq < 2) ? 4 * cq + 2 : 4 * cq - 5;   // f2(2cq+1)
    #pragma unroll
    for (int nt = 0; nt < 8; nt++) {
        int colb = h * DH + nt * 8;
        float* pa = att + ((size_t)b * SEQ + row_a) * INNER + colb;
        float* pb = att + ((size_t)b * SEQ + row_b) * INNER + colb;
        pa[s0off] = cvt_tf32_f(o[nt][0] * inv0);
        pa[s1off] = cvt_tf32_f(o[nt][1] * inv0);
        pb[s0off] = cvt_tf32_f(o[nt][2] * inv1);
        pb[s1off] = cvt_tf32_f(o[nt][3] * inv1);
    }
}

// ===========================================================================
extern "C" void kernel_launch(void* const* d_in, const int* in_sizes, int n_in,
                              void* d_out, int out_size) {
    const float* x     = (const float*)d_in[0];
    const float* gamma = (const float*)d_in[1];
    const float* beta  = (const float*)d_in[2];
    const float* w_qkv = (const float*)d_in[3];
    const float* w_out = (const float*)d_in[4];
    float* out = (float*)d_out;

    float *xn, *qkv, *att, *wqkvT, *woutT;
    cudaGetSymbolAddress((void**)&xn,    g_xn);
    cudaGetSymbolAddress((void**)&qkv,   g_qkv);
    cudaGetSymbolAddress((void**)&att,   g_att);
    cudaGetSymbolAddress((void**)&wqkvT, g_wqkvT);
    cudaGetSymbolAddress((void**)&woutT, g_woutT);

    cudaFuncSetAttribute(gemm_tf32<true>,  cudaFuncAttributeMaxDynamicSharedMemorySize, GEMM_SMEM);
    cudaFuncSetAttribute(gemm_tf32<false>, cudaFuncAttributeMaxDynamicSharedMemorySize, GEMM_SMEM);
    cudaFuncSetAttribute(attn_mma, cudaFuncAttributeMaxDynamicSharedMemorySize, ATTN_SMEM);

    ln_kernel<<<ROWS, 256>>>(x, gamma, beta, xn);
    // wqkvT: K-interleave columns; d-interleave q/k rows (rows < 2*INNER)
    transpose_cvt<<<dim3(QKVW / 32, DIMD / 32), dim3(32, 8)>>>(w_qkv, wqkvT, DIMD, QKVW, 2 * INNER);
    // woutT: K-interleave columns only
    transpose_cvt<<<dim3(DIMD / 32, INNER / 32), dim3(32, 8)>>>(w_out, woutT, INNER, DIMD, 0);
    gemm_tf32<true><<<dim3(QKVW / 128, ROWS / 128), 256, GEMM_SMEM>>>(xn, wqkvT, qkv, ROWS, QKVW, DIMD);
    attn_mma<<<dim3(SEQ / 128, HEADS, BATCH), 256, ATTN_SMEM>>>(qkv, att);
    gemm_tf32<false><<<dim3(DIMD / 128, ROWS / 128), 256, GEMM_SMEM>>>(att, woutT, out, ROWS, DIMD, INNER);
}

// round 9
// speedup vs baseline: 1.6853x; 1.3375x over previous
#include <cuda_runtime.h>
#include <cuda_fp16.h>
#include <math.h>
#include <cstdint>

#define DIMD   1024
#define HEADS  16
#define DH     64
#define INNER  1024
#define BATCH  4
#define SEQ    2048
#define ROWS   (BATCH*SEQ)      // 8192
#define QKVW   (3*INNER)        // 3072

// Scratch (device globals: allocation-free contract). All fp16, K-dims
// pair-interleaved (fp2i) for LDS.64 fragment loads.
__device__ __half g_xn   [ROWS*DIMD];
__device__ __half g_qkv  [ROWS*QKVW];
__device__ __half g_att  [ROWS*INNER];
__device__ __half g_wqkvT[QKVW*DIMD];
__device__ __half g_woutT[DIMD*INNER];

// pair-interleave within 16-group: keeps element parity, permutes pair index j
// (j<4 ? 2j : 2j-7) so halves (2c,2c+1,2c+8,2c+9) become 4 adjacent halves.
__host__ __device__ __forceinline__ int fp2i(int x) {
    int j = (x >> 1) & 7;
    int jq = (j < 4) ? (2 * j) : (2 * j - 7);
    return (x & ~15) | (jq << 1) | (x & 1);
}

__device__ __forceinline__ void mma_f16(float* d, const uint32_t* a, const uint32_t* b) {
    asm volatile(
        "mma.sync.aligned.m16n8k16.row.col.f32.f16.f16.f32 "
        "{%0,%1,%2,%3}, {%4,%5,%6,%7}, {%8,%9}, {%0,%1,%2,%3};"
        : "+f"(d[0]), "+f"(d[1]), "+f"(d[2]), "+f"(d[3])
        : "r"(a[0]), "r"(a[1]), "r"(a[2]), "r"(a[3]), "r"(b[0]), "r"(b[1]));
}

__device__ __forceinline__ void ldmatrix_x4_trans(uint32_t& r0, uint32_t& r1,
                                                  uint32_t& r2, uint32_t& r3,
                                                  uint32_t addr) {
    asm volatile("ldmatrix.sync.aligned.m8n8.x4.trans.shared.b16 {%0,%1,%2,%3}, [%4];"
                 : "=r"(r0), "=r"(r1), "=r"(r2), "=r"(r3) : "r"(addr));
}

__device__ __forceinline__ void cp_async16(uint32_t smem_dst, const void* gmem_src) {
    asm volatile("cp.async.cg.shared.global [%0], [%1], 16;" :: "r"(smem_dst), "l"(gmem_src));
}
#define CP_COMMIT() asm volatile("cp.async.commit_group;" ::: "memory")
#define CP_WAIT(n)  asm volatile("cp.async.wait_group %0;" :: "n"(n) : "memory")

__device__ __forceinline__ uint32_t h2u(__half2 h) { return *reinterpret_cast<uint32_t*>(&h); }

// ===========================================================================
// LayerNorm: one block per row; OUTPUT fp16, pair-interleaved columns.
// ===========================================================================
__global__ void ln_kernel(const float* __restrict__ x,
                          const float* __restrict__ gamma,
                          const float* __restrict__ beta,
                          __half* __restrict__ out) {
    __shared__ float srow[DIMD];
    int row = blockIdx.x;
    int tid = threadIdx.x;
    const float4* xr = reinterpret_cast<const float4*>(x + (size_t)row * DIMD);
    float4 v = xr[tid];
    float s  = v.x + v.y + v.z + v.w;
    float ss = v.x*v.x + v.y*v.y + v.z*v.z + v.w*v.w;
    #pragma unroll
    for (int o = 16; o > 0; o >>= 1) {
        s  += __shfl_xor_sync(0xFFFFFFFFu, s,  o);
        ss += __shfl_xor_sync(0xFFFFFFFFu, ss, o);
    }
    __shared__ float rs[8], rq[8];
    int w = tid >> 5, l = tid & 31;
    if (l == 0) { rs[w] = s; rq[w] = ss; }
    __syncthreads();
    if (w == 0) {
        s  = (l < 8) ? rs[l] : 0.f;
        ss = (l < 8) ? rq[l] : 0.f;
        #pragma unroll
        for (int o = 4; o > 0; o >>= 1) {
            s  += __shfl_xor_sync(0xFFFFFFFFu, s,  o);
            ss += __shfl_xor_sync(0xFFFFFFFFu, ss, o);
        }
        if (l == 0) { rs[0] = s; rq[0] = ss; }
    }
    __syncthreads();
    float mu   = rs[0] * (1.0f / DIMD);
    float var  = rq[0] * (1.0f / DIMD) - mu * mu;
    float rstd = rsqrtf(var + 1e-5f);
    float4 g4 = reinterpret_cast<const float4*>(gamma)[tid];
    float4 b4 = reinterpret_cast<const float4*>(beta)[tid];
    srow[tid*4+0] = (v.x - mu) * rstd * g4.x + b4.x;
    srow[tid*4+1] = (v.y - mu) * rstd * g4.y + b4.y;
    srow[tid*4+2] = (v.z - mu) * rstd * g4.z + b4.z;
    srow[tid*4+3] = (v.w - mu) * rstd * g4.w + b4.w;
    __syncthreads();
    __half* o = out + (size_t)row * DIMD;
    #pragma unroll
    for (int t = 0; t < 2; t++) {
        int sp = tid * 2 + t;            // stored pair index 0..511
        int g  = (sp >> 3) << 4;         // 16-group base (half index)
        int p  = sp & 7;
        int j  = (p & 1) ? ((p + 7) >> 1) : (p >> 1);   // inverse perm
        __half2 h = __floats2half2_rn(srow[g + 2*j], srow[g + 2*j + 1]);
        *reinterpret_cast<uint32_t*>(&o[g + p * 2]) = h2u(h);
    }
}

// ===========================================================================
// Transpose + fp16 + permutations: in fp32 [R][Cc] -> out fp16 [Cc][R].
// Columns (K dim) pair-interleaved; rows < rowlim also pair-interleaved
// (d-interleave for the q/k sections of wqkvT).
// ===========================================================================
__global__ void transpose_cvt(const float* __restrict__ in, __half* __restrict__ out,
                              int R, int Cc, int rowlim) {
    __shared__ float t[32][33];
    int c0 = blockIdx.x * 32, r0 = blockIdx.y * 32;
    int x = threadIdx.x, y = threadIdx.y;   // 32 x 8
    #pragma unroll
    for (int i = 0; i < 32; i += 8)
        t[y + i][x] = in[(size_t)(r0 + y + i) * Cc + c0 + x];
    __syncthreads();
    int colp = r0 + fp2i(x);
    #pragma unroll
    for (int i = 0; i < 32; i += 8) {
        int rown = c0 + y + i;
        int rowp = (rown < rowlim) ? fp2i(rown) : rown;
        out[(size_t)rowp * R + colp] = __float2half_rn(t[x][y + i]);
    }
}

// ===========================================================================
// fp16 mma.sync GEMM, cp.async 2-stage. C[M,Nn] = A[M,K] @ BT[Nn,K]^T.
// A, BT fp16 with pair-interleaved K. CTA 128x128, 256 thr, warp 64x32.
// HALF_OUT: write fp16 half2 (intermediates); else fp32.
// ===========================================================================
#define GBK   32                          // k halves per chunk
#define GSTR  56                          // row stride (halves), conflict-free
#define GTILE (128 * GSTR)                // halves per tile
#define GEMM_SMEM (4 * GTILE * 2)         // 57344 B

template <bool HALF_OUT>
__global__ __launch_bounds__(256, 2)
void gemm_f16(const __half* __restrict__ A, const __half* __restrict__ BT,
              void* __restrict__ Cv, int M, int Nn, int K) {
    extern __shared__ __half smh[];

    int tid  = threadIdx.x;
    int lane = tid & 31;
    int wid  = tid >> 5;
    int wm   = wid >> 2;
    int wn   = wid & 3;

    const __half* Ab = A  + (size_t)blockIdx.y * 128 * K;
    const __half* Bb = BT + (size_t)blockIdx.x * 128 * K;

    float acc[4][4][4];
    #pragma unroll
    for (int i = 0; i < 4; i++)
        #pragma unroll
        for (int j = 0; j < 4; j++)
            #pragma unroll
            for (int k = 0; k < 4; k++) acc[i][j][k] = 0.f;

    const int nchunks = K / GBK;
    uint32_t smbase = (uint32_t)__cvta_generic_to_shared(smh);

    auto stage = [&](int c) {
        int buf = c & 1;
        uint32_t sA = smbase + (buf * GTILE) * 2;
        uint32_t sB = smbase + ((2 + buf) * GTILE) * 2;
        const __half* Ac = Ab + c * GBK;
        const __half* Bc = Bb + c * GBK;
        #pragma unroll
        for (int i = 0; i < 2; i++) {
            int idx = i * 256 + tid;           // 0..511
            int m = idx >> 2, k8 = (idx & 3) << 3;   // 8 halves = 16B
            cp_async16(sA + (m * GSTR + k8) * 2, Ac + (size_t)m * K + k8);
            cp_async16(sB + (m * GSTR + k8) * 2, Bc + (size_t)m * K + k8);
        }
    };

    stage(0);
    CP_COMMIT();

    int r  = lane >> 2;
    int cq = lane & 3;

    for (int c = 0; c < nchunks; c++) {
        if (c + 1 < nchunks) {
            stage(c + 1);
            CP_COMMIT();
            CP_WAIT(1);
        } else {
            CP_WAIT(0);
        }
        __syncthreads();

        const __half* As = smh + (c & 1) * GTILE;
        const __half* Bs = smh + (2 + (c & 1)) * GTILE;

        #pragma unroll
        for (int ks = 0; ks < 2; ks++) {
            uint32_t a[4][4], b[4][2];
            #pragma unroll
            for (int mt = 0; mt < 4; mt++) {
                const __half* ap = &As[(wm * 64 + mt * 16 + r) * GSTR + ks * 16 + 4 * cq];
                uint2 lo = *reinterpret_cast<const uint2*>(ap);
                uint2 hi = *reinterpret_cast<const uint2*>(ap + 8 * GSTR);
                a[mt][0] = lo.x; a[mt][1] = hi.x; a[mt][2] = lo.y; a[mt][3] = hi.y;
            }
            #pragma unroll
            for (int nt = 0; nt < 4; nt++) {
                const __half* bp = &Bs[(wn * 32 + nt * 8 + r) * GSTR + ks * 16 + 4 * cq];
                uint2 bb = *reinterpret_cast<const uint2*>(bp);
                b[nt][0] = bb.x; b[nt][1] = bb.y;
            }
            #pragma unroll
            for (int mt = 0; mt < 4; mt++)
                #pragma unroll
                for (int nt = 0; nt < 4; nt++)
                    mma_f16(acc[mt][nt], a[mt], b[nt]);
        }
        __syncthreads();
    }

    #pragma unroll
    for (int mt = 0; mt < 4; mt++) {
        int row0 = blockIdx.y * 128 + wm * 64 + mt * 16 + r;
        #pragma unroll
        for (int nt = 0; nt < 4; nt++) {
            int col0 = blockIdx.x * 128 + wn * 32 + nt * 8 + cq * 2;
            if (HALF_OUT) {
                __half* C = (__half*)Cv;
                *reinterpret_cast<uint32_t*>(C + (size_t)row0 * Nn + col0) =
                    h2u(__floats2half2_rn(acc[mt][nt][0], acc[mt][nt][1]));
                *reinterpret_cast<uint32_t*>(C + (size_t)(row0 + 8) * Nn + col0) =
                    h2u(__floats2half2_rn(acc[mt][nt][2], acc[mt][nt][3]));
            } else {
                float* C = (float*)Cv;
                *reinterpret_cast<float2*>(C + (size_t)row0 * Nn + col0) =
                    make_float2(acc[mt][nt][0], acc[mt][nt][1]);
                *reinterpret_cast<float2*>(C + (size_t)(row0 + 8) * Nn + col0) =
                    make_float2(acc[mt][nt][2], acc[mt][nt][3]);
            }
        }
    }
}

// ===========================================================================
// Flash attention fp16 mma. One block = (b,h), BQ=128, BC=64, 8 warps.
// q/k features pair-interleaved (baked into wqkvT rows); V natural.
// K frags: LDS.64. V frags: ldmatrix.x4.trans. P: fp16 in warp-private smem.
// ===========================================================================
#define KSTR 72
#define KTILE (64 * KSTR)                 // halves
#define ASM_P (4 * KTILE)                 // after K0,K1,V0,V1
#define PSTR 72
#define ATTN_SMEM ((4 * KTILE + 128 * PSTR) * 2)   // 55296 B

__global__ __launch_bounds__(256)
void attn_mma(const __half* __restrict__ qkv, __half* __restrict__ att) {
    extern __shared__ __half smh[];
    __half* sP = smh + ASM_P;

    int tid = threadIdx.x, lane = tid & 31, wid = tid >> 5;
    int r = lane >> 2, cq = lane & 3;
    int qt = gridDim.x - 1 - blockIdx.x;     // longest tiles first
    int h = blockIdx.y, b = blockIdx.z;
    int q0 = qt * 128;

    const __half* qbase = qkv + (size_t)b * SEQ * QKVW + h * DH;
    const __half* kbase = qbase + INNER;
    const __half* vbase = qbase + 2 * INNER;

    uint32_t smb = (uint32_t)__cvta_generic_to_shared(smh);
    uint32_t spb = smb + ASM_P * 2;

    const int nchunk = 2 * qt + 2;

    auto stage = [&](int c) {
        int buf = c & 1;
        uint32_t sK = smb + (buf * KTILE) * 2;
        uint32_t sV = smb + ((2 + buf) * KTILE) * 2;
        const __half* kc = kbase + (size_t)c * 64 * QKVW;
        const __half* vc = vbase + (size_t)c * 64 * QKVW;
        #pragma unroll
        for (int i = 0; i < 2; i++) {
            int idx = i * 256 + tid;           // 0..511
            int row = idx >> 3, d8 = (idx & 7) << 3;
            cp_async16(sK + (row * KSTR + d8) * 2, kc + (size_t)row * QKVW + d8);
            cp_async16(sV + (row * KSTR + d8) * 2, vc + (size_t)row * QKVW + d8);
        }
    };

    // Q tile into sP region
    #pragma unroll
    for (int i = 0; i < 4; i++) {
        int idx = i * 256 + tid;               // 0..1023
        int row = idx >> 3, d8 = (idx & 7) << 3;
        cp_async16(spb + (row * PSTR + d8) * 2, qbase + (size_t)(q0 + row) * QKVW + d8);
    }
    stage(0);
    CP_COMMIT();

    // ldmatrix per-lane base offset for V (halves)
    int sub = lane >> 3;
    int vlb = ((sub & 1) * 8 + (lane & 7)) * KSTR + (sub >> 1) * 8;

    uint32_t qf[4][4];
    float m0 = -1e30f, m1 = -1e30f, l0 = 0.f, l1 = 0.f;
    float o[8][4];
    #pragma unroll
    for (int nt = 0; nt < 8; nt++)
        #pragma unroll
        for (int j = 0; j < 4; j++) o[nt][j] = 0.f;

    const __half2 qsc = __floats2half2_rn(0.125f, 0.125f);

    for (int c = 0; c < nchunk; c++) {
        if (c + 1 < nchunk) {
            stage(c + 1);
            CP_COMMIT();
            CP_WAIT(1);
        } else {
            CP_WAIT(0);
        }
        __syncthreads();

        if (c == 0) {
            #pragma unroll
            for (int kt = 0; kt < 4; kt++) {
                const __half* p = &sP[(wid * 16 + r) * PSTR + kt * 16 + 4 * cq];
                uint2 lo = *reinterpret_cast<const uint2*>(p);
                uint2 hi = *reinterpret_cast<const uint2*>(p + 8 * PSTR);
                qf[kt][0] = h2u(__hmul2(*reinterpret_cast<__half2*>(&lo.x), qsc));
                qf[kt][1] = h2u(__hmul2(*reinterpret_cast<__half2*>(&hi.x), qsc));
                qf[kt][2] = h2u(__hmul2(*reinterpret_cast<__half2*>(&lo.y), qsc));
                qf[kt][3] = h2u(__hmul2(*reinterpret_cast<__half2*>(&hi.y), qsc));
            }
            __syncthreads();   // Q reads done before P overwrites sP
        }

        const __half* sK = smh + (c & 1) * KTILE;
        uint32_t sVu = smb + ((2 + (c & 1)) * KTILE) * 2;

        int wrow0 = q0 + wid * 16;
        if (wrow0 + 15 >= c * 64) {
            // ---- S = Q @ K^T
            float s[8][4];
            #pragma unroll
            for (int nt = 0; nt < 8; nt++)
                #pragma unroll
                for (int j = 0; j < 4; j++) s[nt][j] = 0.f;
            #pragma unroll
            for (int kt = 0; kt < 4; kt++) {
                #pragma unroll
                for (int nt = 0; nt < 8; nt++) {
                    uint2 kk = *reinterpret_cast<const uint2*>(
                        &sK[(nt * 8 + r) * KSTR + kt * 16 + 4 * cq]);
                    uint32_t bf[2] = { kk.x, kk.y };
                    mma_f16(s[nt], qf[kt], bf);
                }
            }

            // ---- causal mask
            if (c * 64 + 63 > wrow0) {
                int row_a = wrow0 + r, row_b = wrow0 + r + 8;
                #pragma unroll
                for (int nt = 0; nt < 8; nt++) {
                    int col = c * 64 + nt * 8 + 2 * cq;
                    if (col     > row_a) s[nt][0] = -1e30f;
                    if (col + 1 > row_a) s[nt][1] = -1e30f;
                    if (col     > row_b) s[nt][2] = -1e30f;
                    if (col + 1 > row_b) s[nt][3] = -1e30f;
                }
            }

            // ---- online softmax
            float mt0 = -1e30f, mt1 = -1e30f;
            #pragma unroll
            for (int nt = 0; nt < 8; nt++) {
                mt0 = fmaxf(mt0, fmaxf(s[nt][0], s[nt][1]));
                mt1 = fmaxf(mt1, fmaxf(s[nt][2], s[nt][3]));
            }
            mt0 = fmaxf(mt0, __shfl_xor_sync(0xFFFFFFFFu, mt0, 1));
            mt0 = fmaxf(mt0, __shfl_xor_sync(0xFFFFFFFFu, mt0, 2));
            mt1 = fmaxf(mt1, __shfl_xor_sync(0xFFFFFFFFu, mt1, 1));
            mt1 = fmaxf(mt1, __shfl_xor_sync(0xFFFFFFFFu, mt1, 2));

            float mn0 = fmaxf(m0, mt0), mn1 = fmaxf(m1, mt1);
            float a0 = __expf(m0 - mn0), a1 = __expf(m1 - mn1);
            m0 = mn0; m1 = mn1;
            float rs0 = 0.f, rs1 = 0.f;
            #pragma unroll
            for (int nt = 0; nt < 8; nt++) {
                s[nt][0] = __expf(s[nt][0] - mn0);
                s[nt][1] = __expf(s[nt][1] - mn0);
                s[nt][2] = __expf(s[nt][2] - mn1);
                s[nt][3] = __expf(s[nt][3] - mn1);
                rs0 += s[nt][0] + s[nt][1];
                rs1 += s[nt][2] + s[nt][3];
            }
            rs0 += __shfl_xor_sync(0xFFFFFFFFu, rs0, 1);
            rs0 += __shfl_xor_sync(0xFFFFFFFFu, rs0, 2);
            rs1 += __shfl_xor_sync(0xFFFFFFFFu, rs1, 1);
            rs1 += __shfl_xor_sync(0xFFFFFFFFu, rs1, 2);
            l0 = l0 * a0 + rs0;
            l1 = l1 * a1 + rs1;
            #pragma unroll
            for (int nt = 0; nt < 8; nt++) {
                o[nt][0] *= a0; o[nt][1] *= a0;
                o[nt][2] *= a1; o[nt][3] *= a1;
            }

            // ---- P -> warp-private smem, fp16, kv pair-interleaved
            {
                __half* pr0 = &sP[(wid * 16 + r) * PSTR];
                __half* pr1 = &sP[(wid * 16 + r + 8) * PSTR];
                #pragma unroll
                for (int nt = 0; nt < 8; nt++) {
                    int g2 = nt >> 1;
                    int jl = ((nt & 1) << 2) | cq;
                    int sp = (jl < 4) ? (2 * jl) : (2 * jl - 7);
                    int pos = g2 * 16 + sp * 2;
                    *reinterpret_cast<uint32_t*>(&pr0[pos]) =
                        h2u(__floats2half2_rn(s[nt][0], s[nt][1]));
                    *reinterpret_cast<uint32_t*>(&pr1[pos]) =
                        h2u(__floats2half2_rn(s[nt][2], s[nt][3]));
                }
            }
            __syncwarp();

            // ---- O += P @ V (V natural [kv][d], frags via ldmatrix.trans)
            #pragma unroll
            for (int kt = 0; kt < 4; kt++) {
                uint32_t pf[4];
                const __half* pp = &sP[(wid * 16 + r) * PSTR + kt * 16 + 4 * cq];
                uint2 plo = *reinterpret_cast<const uint2*>(pp);
                uint2 phi = *reinterpret_cast<const uint2*>(pp + 8 * PSTR);
                pf[0] = plo.x; pf[1] = phi.x; pf[2] = plo.y; pf[3] = phi.y;
                #pragma unroll
                for (int ntp = 0; ntp < 4; ntp++) {
                    uint32_t b0a, b1a, b0b, b1b;
                    uint32_t addr = sVu + (vlb + kt * 16 * KSTR + ntp * 16) * 2;
                    ldmatrix_x4_trans(b0a, b1a, b0b, b1b, addr);
                    uint32_t bfa[2] = { b0a, b1a };
                    uint32_t bfb[2] = { b0b, b1b };
                    mma_f16(o[2 * ntp],     pf, bfa);
                    mma_f16(o[2 * ntp + 1], pf, bfb);
                }
            }
        }
        __syncthreads();
    }

    // ---- epilogue: fp16, pair-interleaved columns (for GEMM2's K)
    float inv0 = 1.f / l0, inv1 = 1.f / l1;
    int row_a = q0 + wid * 16 + r, row_b = row_a + 8;
    #pragma unroll
    for (int nt = 0; nt < 8; nt++) {
        int g2 = nt >> 1;
        int jl = ((nt & 1) << 2) | cq;
        int sp = (jl < 4) ? (2 * jl) : (2 * jl - 7);
        int colb = h * DH + g2 * 16 + sp * 2;
        *reinterpret_cast<uint32_t*>(att + ((size_t)b * SEQ + row_a) * INNER + colb) =
            h2u(__floats2half2_rn(o[nt][0] * inv0, o[nt][1] * inv0));
        *reinterpret_cast<uint32_t*>(att + ((size_t)b * SEQ + row_b) * INNER + colb) =
            h2u(__floats2half2_rn(o[nt][2] * inv1, o[nt][3] * inv1));
    }
}

// ===========================================================================
extern "C" void kernel_launch(void* const* d_in, const int* in_sizes, int n_in,
                              void* d_out, int out_size) {
    const float* x     = (const float*)d_in[0];
    const float* gamma = (const float*)d_in[1];
    const float* beta  = (const float*)d_in[2];
    const float* w_qkv = (const float*)d_in[3];
    const float* w_out = (const float*)d_in[4];
    float* out = (float*)d_out;

    __half *xn, *qkv, *att, *wqkvT, *woutT;
    cudaGetSymbolAddress((void**)&xn,    g_xn);
    cudaGetSymbolAddress((void**)&qkv,   g_qkv);
    cudaGetSymbolAddress((void**)&att,   g_att);
    cudaGetSymbolAddress((void**)&wqkvT, g_wqkvT);
    cudaGetSymbolAddress((void**)&woutT, g_woutT);

    cudaFuncSetAttribute(gemm_f16<true>,  cudaFuncAttributeMaxDynamicSharedMemorySize, GEMM_SMEM);
    cudaFuncSetAttribute(gemm_f16<false>, cudaFuncAttributeMaxDynamicSharedMemorySize, GEMM_SMEM);
    cudaFuncSetAttribute(attn_mma, cudaFuncAttributeMaxDynamicSharedMemorySize, ATTN_SMEM);

    ln_kernel<<<ROWS, 256>>>(x, gamma, beta, xn);
    transpose_cvt<<<dim3(QKVW / 32, DIMD / 32), dim3(32, 8)>>>(w_qkv, wqkvT, DIMD, QKVW, 2 * INNER);
    transpose_cvt<<<dim3(DIMD / 32, INNER / 32), dim3(32, 8)>>>(w_out, woutT, INNER, DIMD, 0);
    gemm_f16<true><<<dim3(QKVW / 128, ROWS / 128), 256, GEMM_SMEM>>>(xn, wqkvT, qkv, ROWS, QKVW, DIMD);
    attn_mma<<<dim3(SEQ / 128, HEADS, BATCH), 256, ATTN_SMEM>>>(qkv, att);
    gemm_f16<false><<<dim3(DIMD / 128, ROWS / 128), 256, GEMM_SMEM>>>(att, woutT, out, ROWS, DIMD, INNER);
}

// round 10
// speedup vs baseline: 2.1359x; 1.2673x over previous
#include <cuda_runtime.h>
#include <cuda_fp16.h>
#include <math.h>
#include <cstdint>

#define DIMD   1024
#define HEADS  16
#define DH     64
#define INNER  1024
#define BATCH  4
#define SEQ    2048
#define ROWS   (BATCH*SEQ)      // 8192
#define QKVW   (3*INNER)        // 3072

// Scratch (device globals). All fp16, NATURAL layouts.
__device__ __half g_xn   [ROWS*DIMD];
__device__ __half g_qkv  [ROWS*QKVW];
__device__ __half g_att  [ROWS*INNER];
__device__ __half g_wqkvT[QKVW*DIMD];   // [N][K]
__device__ __half g_woutT[DIMD*INNER];  // [N][K]

__device__ __forceinline__ void mma_f16(float* d, const uint32_t* a, const uint32_t* b) {
    asm volatile(
        "mma.sync.aligned.m16n8k16.row.col.f32.f16.f16.f32 "
        "{%0,%1,%2,%3}, {%4,%5,%6,%7}, {%8,%9}, {%0,%1,%2,%3};"
        : "+f"(d[0]), "+f"(d[1]), "+f"(d[2]), "+f"(d[3])
        : "r"(a[0]), "r"(a[1]), "r"(a[2]), "r"(a[3]), "r"(b[0]), "r"(b[1]));
}

__device__ __forceinline__ void ldmx4(uint32_t& r0, uint32_t& r1, uint32_t& r2,
                                      uint32_t& r3, uint32_t addr) {
    asm volatile("ldmatrix.sync.aligned.m8n8.x4.shared.b16 {%0,%1,%2,%3}, [%4];"
                 : "=r"(r0), "=r"(r1), "=r"(r2), "=r"(r3) : "r"(addr));
}
__device__ __forceinline__ void ldmx4t(uint32_t& r0, uint32_t& r1, uint32_t& r2,
                                       uint32_t& r3, uint32_t addr) {
    asm volatile("ldmatrix.sync.aligned.m8n8.x4.trans.shared.b16 {%0,%1,%2,%3}, [%4];"
                 : "=r"(r0), "=r"(r1), "=r"(r2), "=r"(r3) : "r"(addr));
}

__device__ __forceinline__ void cp_async16(uint32_t smem_dst, const void* gmem_src) {
    asm volatile("cp.async.cg.shared.global [%0], [%1], 16;" :: "r"(smem_dst), "l"(gmem_src));
}
#define CP_COMMIT() asm volatile("cp.async.commit_group;" ::: "memory")
#define CP_WAIT(n)  asm volatile("cp.async.wait_group %0;" :: "n"(n) : "memory")

__device__ __forceinline__ uint32_t h2u(__half2 h) { return *reinterpret_cast<uint32_t*>(&h); }
__device__ __forceinline__ uint32_t packh2(float a, float b) {
    return h2u(__floats2half2_rn(a, b));
}

// ===========================================================================
// LayerNorm: one block per row; OUTPUT fp16 natural.
// ===========================================================================
__global__ void ln_kernel(const float* __restrict__ x,
                          const float* __restrict__ gamma,
                          const float* __restrict__ beta,
                          __half* __restrict__ out) {
    int row = blockIdx.x;
    int tid = threadIdx.x;
    const float4* xr = reinterpret_cast<const float4*>(x + (size_t)row * DIMD);
    float4 v = xr[tid];
    float s  = v.x + v.y + v.z + v.w;
    float ss = v.x*v.x + v.y*v.y + v.z*v.z + v.w*v.w;
    #pragma unroll
    for (int o = 16; o > 0; o >>= 1) {
        s  += __shfl_xor_sync(0xFFFFFFFFu, s,  o);
        ss += __shfl_xor_sync(0xFFFFFFFFu, ss, o);
    }
    __shared__ float rs[8], rq[8];
    int w = tid >> 5, l = tid & 31;
    if (l == 0) { rs[w] = s; rq[w] = ss; }
    __syncthreads();
    if (w == 0) {
        s  = (l < 8) ? rs[l] : 0.f;
        ss = (l < 8) ? rq[l] : 0.f;
        #pragma unroll
        for (int o = 4; o > 0; o >>= 1) {
            s  += __shfl_xor_sync(0xFFFFFFFFu, s,  o);
            ss += __shfl_xor_sync(0xFFFFFFFFu, ss, o);
        }
        if (l == 0) { rs[0] = s; rq[0] = ss; }
    }
    __syncthreads();
    float mu   = rs[0] * (1.0f / DIMD);
    float var  = rq[0] * (1.0f / DIMD) - mu * mu;
    float rstd = rsqrtf(var + 1e-5f);
    float4 g4 = reinterpret_cast<const float4*>(gamma)[tid];
    float4 b4 = reinterpret_cast<const float4*>(beta)[tid];
    uint2 o2;
    o2.x = packh2((v.x - mu) * rstd * g4.x + b4.x, (v.y - mu) * rstd * g4.y + b4.y);
    o2.y = packh2((v.z - mu) * rstd * g4.z + b4.z, (v.w - mu) * rstd * g4.w + b4.w);
    *reinterpret_cast<uint2*>(out + (size_t)row * DIMD + tid * 4) = o2;
}

// ===========================================================================
// Transpose + fp16: in fp32 [R][Cc] -> out fp16 [Cc][R], natural.
// ===========================================================================
__global__ void transpose_cvt(const float* __restrict__ in, __half* __restrict__ out,
                              int R, int Cc) {
    __shared__ float t[32][33];
    int c0 = blockIdx.x * 32, r0 = blockIdx.y * 32;
    int x = threadIdx.x, y = threadIdx.y;   // 32 x 8
    #pragma unroll
    for (int i = 0; i < 32; i += 8)
        t[y + i][x] = in[(size_t)(r0 + y + i) * Cc + c0 + x];
    __syncthreads();
    #pragma unroll
    for (int i = 0; i < 32; i += 8)
        out[(size_t)(c0 + y + i) * R + r0 + x] = __float2half_rn(t[x][y + i]);
}

// ===========================================================================
// fp16 mma.sync GEMM, cp.async 2-stage, ldmatrix fragments.
// C[M,Nn] = A[M,K] @ BT[Nn,K]^T. CTA 128x128, 256 thr, warp 64x32.
// ===========================================================================
#define GBK   32                          // k halves per chunk
#define GSTR  56                          // row stride (halves): banks 28i%32 distinct
#define GTILE (128 * GSTR)
#define GEMM_SMEM (4 * GTILE * 2)         // 57344 B

template <bool HALF_OUT>
__global__ __launch_bounds__(256, 2)
void gemm_f16(const __half* __restrict__ A, const __half* __restrict__ BT,
              void* __restrict__ Cv, int M, int Nn, int K) {
    extern __shared__ __half smh[];

    int tid  = threadIdx.x;
    int lane = tid & 31;
    int wid  = tid >> 5;
    int wm   = wid >> 2;
    int wn   = wid & 3;

    const __half* Ab = A  + (size_t)blockIdx.y * 128 * K;
    const __half* Bb = BT + (size_t)blockIdx.x * 128 * K;

    float acc[4][4][4];
    #pragma unroll
    for (int i = 0; i < 4; i++)
        #pragma unroll
        for (int j = 0; j < 4; j++)
            #pragma unroll
            for (int k = 0; k < 4; k++) acc[i][j][k] = 0.f;

    const int nchunks = K / GBK;
    uint32_t smbase = (uint32_t)__cvta_generic_to_shared(smh);

    auto stage = [&](int c) {
        int buf = c & 1;
        uint32_t sA = smbase + (buf * GTILE) * 2;
        uint32_t sB = smbase + ((2 + buf) * GTILE) * 2;
        const __half* Ac = Ab + c * GBK;
        const __half* Bc = Bb + c * GBK;
        #pragma unroll
        for (int i = 0; i < 2; i++) {
            int idx = i * 256 + tid;
            int m = idx >> 2, k8 = (idx & 3) << 3;
            cp_async16(sA + (m * GSTR + k8) * 2, Ac + (size_t)m * K + k8);
            cp_async16(sB + (m * GSTR + k8) * 2, Bc + (size_t)m * K + k8);
        }
    };

    stage(0);
    CP_COMMIT();

    int r  = lane >> 2;
    int cq = lane & 3;
    // ldmatrix lane-address components
    int arow = lane & 15, akoff = (lane >> 4) << 3;                 // A/Q pattern
    int brow = ((lane >> 4) << 3) + (lane & 7), bkoff = ((lane >> 3) & 1) << 3;  // B pattern

    for (int c = 0; c < nchunks; c++) {
        if (c + 1 < nchunks) {
            stage(c + 1);
            CP_COMMIT();
            CP_WAIT(1);
        } else {
            CP_WAIT(0);
        }
        __syncthreads();

        uint32_t sAu = smbase + ((c & 1) * GTILE) * 2;
        uint32_t sBu = smbase + ((2 + (c & 1)) * GTILE) * 2;

        #pragma unroll
        for (int ks = 0; ks < 2; ks++) {
            uint32_t a[4][4], b[2][4];
            #pragma unroll
            for (int mt = 0; mt < 4; mt++) {
                uint32_t addr = sAu + (((wm * 64 + mt * 16 + arow) * GSTR) + ks * 16 + akoff) * 2;
                ldmx4(a[mt][0], a[mt][1], a[mt][2], a[mt][3], addr);
            }
            #pragma unroll
            for (int np = 0; np < 2; np++) {
                uint32_t addr = sBu + (((wn * 32 + np * 16 + brow) * GSTR) + ks * 16 + bkoff) * 2;
                ldmx4(b[np][0], b[np][1], b[np][2], b[np][3], addr);
            }
            #pragma unroll
            for (int mt = 0; mt < 4; mt++)
                #pragma unroll
                for (int nt = 0; nt < 4; nt++)
                    mma_f16(acc[mt][nt], a[mt], &b[nt >> 1][(nt & 1) * 2]);
        }
        __syncthreads();
    }

    #pragma unroll
    for (int mt = 0; mt < 4; mt++) {
        int row0 = blockIdx.y * 128 + wm * 64 + mt * 16 + r;
        #pragma unroll
        for (int nt = 0; nt < 4; nt++) {
            int col0 = blockIdx.x * 128 + wn * 32 + nt * 8 + cq * 2;
            if (HALF_OUT) {
                __half* C = (__half*)Cv;
                *reinterpret_cast<uint32_t*>(C + (size_t)row0 * Nn + col0) =
                    packh2(acc[mt][nt][0], acc[mt][nt][1]);
                *reinterpret_cast<uint32_t*>(C + (size_t)(row0 + 8) * Nn + col0) =
                    packh2(acc[mt][nt][2], acc[mt][nt][3]);
            } else {
                float* C = (float*)Cv;
                *reinterpret_cast<float2*>(C + (size_t)row0 * Nn + col0) =
                    make_float2(acc[mt][nt][0], acc[mt][nt][1]);
                *reinterpret_cast<float2*>(C + (size_t)(row0 + 8) * Nn + col0) =
                    make_float2(acc[mt][nt][2], acc[mt][nt][3]);
            }
        }
    }
}

// ===========================================================================
// Flash attention fp16 mma, register-resident P. One block = (b,h),
// BQ=128, BC=64, 8 warps. K/Q frags: ldmatrix.x4; V frags: ldmatrix.x4.trans.
// ===========================================================================
#define KSTR 72
#define KTILE (64 * KSTR)                 // halves
#define ASM_Q (4 * KTILE)                 // Q after K0,K1,V0,V1
#define QSTR 72
#define ATTN_SMEM ((4 * KTILE + 128 * QSTR) * 2)   // 55296 B

__global__ __launch_bounds__(256)
void attn_mma(const __half* __restrict__ qkv, __half* __restrict__ att) {
    extern __shared__ __half smh[];

    int tid = threadIdx.x, lane = tid & 31, wid = tid >> 5;
    int r = lane >> 2, cq = lane & 3;
    int qt = gridDim.x - 1 - blockIdx.x;     // longest tiles first
    int h = blockIdx.y, b = blockIdx.z;
    int q0 = qt * 128;

    const __half* qbase = qkv + (size_t)b * SEQ * QKVW + h * DH;
    const __half* kbase = qbase + INNER;
    const __half* vbase = qbase + 2 * INNER;

    uint32_t smb = (uint32_t)__cvta_generic_to_shared(smh);
    uint32_t sQu = smb + ASM_Q * 2;

    const int nchunk = 2 * qt + 2;

    auto stage = [&](int c) {
        int buf = c & 1;
        uint32_t sK = smb + (buf * KTILE) * 2;
        uint32_t sV = smb + ((2 + buf) * KTILE) * 2;
        const __half* kc = kbase + (size_t)c * 64 * QKVW;
        const __half* vc = vbase + (size_t)c * 64 * QKVW;
        #pragma unroll
        for (int i = 0; i < 2; i++) {
            int idx = i * 256 + tid;
            int row = idx >> 3, d8 = (idx & 7) << 3;
            cp_async16(sK + (row * KSTR + d8) * 2, kc + (size_t)row * QKVW + d8);
            cp_async16(sV + (row * KSTR + d8) * 2, vc + (size_t)row * QKVW + d8);
        }
    };

    // Q tile
    #pragma unroll
    for (int i = 0; i < 4; i++) {
        int idx = i * 256 + tid;
        int row = idx >> 3, d8 = (idx & 7) << 3;
        cp_async16(sQu + (row * QSTR + d8) * 2, qbase + (size_t)(q0 + row) * QKVW + d8);
    }
    stage(0);
    CP_COMMIT();

    // ldmatrix lane-address components
    int arow = lane & 15, akoff = (lane >> 4) << 3;
    int brow = ((lane >> 4) << 3) + (lane & 7), bkoff = ((lane >> 3) & 1) << 3;
    int sub = lane >> 3;
    int vlb = ((sub & 1) * 8 + (lane & 7)) * KSTR + (sub >> 1) * 8;  // V trans pattern

    uint32_t qf[4][4];
    float m0 = -1e30f, m1 = -1e30f, l0 = 0.f, l1 = 0.f;
    float o[8][4];
    #pragma unroll
    for (int nt = 0; nt < 8; nt++)
        #pragma unroll
        for (int j = 0; j < 4; j++) o[nt][j] = 0.f;

    const __half2 qsc = __floats2half2_rn(0.125f, 0.125f);

    for (int c = 0; c < nchunk; c++) {
        if (c + 1 < nchunk) {
            stage(c + 1);
            CP_COMMIT();
            CP_WAIT(1);
        } else {
            CP_WAIT(0);
        }
        __syncthreads();

        if (c == 0) {
            #pragma unroll
            for (int kt = 0; kt < 4; kt++) {
                uint32_t addr = sQu + (((wid * 16 + arow) * QSTR) + kt * 16 + akoff) * 2;
                ldmx4(qf[kt][0], qf[kt][1], qf[kt][2], qf[kt][3], addr);
                #pragma unroll
                for (int j = 0; j < 4; j++)
                    qf[kt][j] = h2u(__hmul2(*reinterpret_cast<__half2*>(&qf[kt][j]), qsc));
            }
        }

        uint32_t sKu = smb + ((c & 1) * KTILE) * 2;
        uint32_t sVu = smb + ((2 + (c & 1)) * KTILE) * 2;

        int wrow0 = q0 + wid * 16;
        if (wrow0 + 15 >= c * 64) {
            // ---- S = Q @ K^T (K frags via ldmatrix.x4, 2 n-tiles each)
            float s[8][4];
            #pragma unroll
            for (int nt = 0; nt < 8; nt++)
                #pragma unroll
                for (int j = 0; j < 4; j++) s[nt][j] = 0.f;
            #pragma unroll
            for (int kt = 0; kt < 4; kt++) {
                #pragma unroll
                for (int np = 0; np < 4; np++) {
                    uint32_t b0, b1, b2, b3;
                    uint32_t addr = sKu + (((np * 16 + brow) * KSTR) + kt * 16 + bkoff) * 2;
                    ldmx4(b0, b1, b2, b3, addr);
                    uint32_t bfa[2] = { b0, b1 };
                    uint32_t bfb[2] = { b2, b3 };
                    mma_f16(s[2 * np],     qf[kt], bfa);
                    mma_f16(s[2 * np + 1], qf[kt], bfb);
                }
            }

            // ---- causal mask
            if (c * 64 + 63 > wrow0) {
                int row_a = wrow0 + r, row_b = wrow0 + r + 8;
                #pragma unroll
                for (int nt = 0; nt < 8; nt++) {
                    int col = c * 64 + nt * 8 + 2 * cq;
                    if (col     > row_a) s[nt][0] = -1e30f;
                    if (col + 1 > row_a) s[nt][1] = -1e30f;
                    if (col     > row_b) s[nt][2] = -1e30f;
                    if (col + 1 > row_b) s[nt][3] = -1e30f;
                }
            }

            // ---- online softmax
            float mt0 = -1e30f, mt1 = -1e30f;
            #pragma unroll
            for (int nt = 0; nt < 8; nt++) {
                mt0 = fmaxf(mt0, fmaxf(s[nt][0], s[nt][1]));
                mt1 = fmaxf(mt1, fmaxf(s[nt][2], s[nt][3]));
            }
            mt0 = fmaxf(mt0, __shfl_xor_sync(0xFFFFFFFFu, mt0, 1));
            mt0 = fmaxf(mt0, __shfl_xor_sync(0xFFFFFFFFu, mt0, 2));
            mt1 = fmaxf(mt1, __shfl_xor_sync(0xFFFFFFFFu, mt1, 1));
            mt1 = fmaxf(mt1, __shfl_xor_sync(0xFFFFFFFFu, mt1, 2));

            float mn0 = fmaxf(m0, mt0), mn1 = fmaxf(m1, mt1);
            float a0 = __expf(m0 - mn0), a1 = __expf(m1 - mn1);
            m0 = mn0; m1 = mn1;
            float rs0 = 0.f, rs1 = 0.f;
            #pragma unroll
            for (int nt = 0; nt < 8; nt++) {
                s[nt][0] = __expf(s[nt][0] - mn0);
                s[nt][1] = __expf(s[nt][1] - mn0);
                s[nt][2] = __expf(s[nt][2] - mn1);
                s[nt][3] = __expf(s[nt][3] - mn1);
                rs0 += s[nt][0] + s[nt][1];
                rs1 += s[nt][2] + s[nt][3];
            }
            rs0 += __shfl_xor_sync(0xFFFFFFFFu, rs0, 1);
            rs0 += __shfl_xor_sync(0xFFFFFFFFu, rs0, 2);
            rs1 += __shfl_xor_sync(0xFFFFFFFFu, rs1, 1);
            rs1 += __shfl_xor_sync(0xFFFFFFFFu, rs1, 2);
            l0 = l0 * a0 + rs0;
            l1 = l1 * a1 + rs1;
            #pragma unroll
            for (int nt = 0; nt < 8; nt++) {
                o[nt][0] *= a0; o[nt][1] *= a0;
                o[nt][2] *= a1; o[nt][3] *= a1;
            }

            // ---- O += P @ V : P converted acc->A-frag in REGISTERS
            #pragma unroll
            for (int kt = 0; kt < 4; kt++) {
                uint32_t pf[4];
                pf[0] = packh2(s[2 * kt][0],     s[2 * kt][1]);
                pf[1] = packh2(s[2 * kt][2],     s[2 * kt][3]);
                pf[2] = packh2(s[2 * kt + 1][0], s[2 * kt + 1][1]);
                pf[3] = packh2(s[2 * kt + 1][2], s[2 * kt + 1][3]);
                #pragma unroll
                for (int ntp = 0; ntp < 4; ntp++) {
                    uint32_t b0a, b1a, b0b, b1b;
                    uint32_t addr = sVu + (vlb + kt * 16 * KSTR + ntp * 16) * 2;
                    ldmx4t(b0a, b1a, b0b, b1b, addr);
                    uint32_t bfa[2] = { b0a, b1a };
                    uint32_t bfb[2] = { b0b, b1b };
                    mma_f16(o[2 * ntp],     pf, bfa);
                    mma_f16(o[2 * ntp + 1], pf, bfb);
                }
            }
        }
        __syncthreads();
    }

    // ---- epilogue: fp16 natural
    float inv0 = 1.f / l0, inv1 = 1.f / l1;
    int row_a = q0 + wid * 16 + r, row_b = row_a + 8;
    #pragma unroll
    for (int nt = 0; nt < 8; nt++) {
        int col = h * DH + nt * 8 + 2 * cq;
        *reinterpret_cast<uint32_t*>(att + ((size_t)b * SEQ + row_a) * INNER + col) =
            packh2(o[nt][0] * inv0, o[nt][1] * inv0);
        *reinterpret_cast<uint32_t*>(att + ((size_t)b * SEQ + row_b) * INNER + col) =
            packh2(o[nt][2] * inv1, o[nt][3] * inv1);
    }
}

// ===========================================================================
extern "C" void kernel_launch(void* const* d_in, const int* in_sizes, int n_in,
                              void* d_out, int out_size) {
    const float* x     = (const float*)d_in[0];
    const float* gamma = (const float*)d_in[1];
    const float* beta  = (const float*)d_in[2];
    const float* w_qkv = (const float*)d_in[3];
    const float* w_out = (const float*)d_in[4];
    float* out = (float*)d_out;

    __half *xn, *qkv, *att, *wqkvT, *woutT;
    cudaGetSymbolAddress((void**)&xn,    g_xn);
    cudaGetSymbolAddress((void**)&qkv,   g_qkv);
    cudaGetSymbolAddress((void**)&att,   g_att);
    cudaGetSymbolAddress((void**)&wqkvT, g_wqkvT);
    cudaGetSymbolAddress((void**)&woutT, g_woutT);

    cudaFuncSetAttribute(gemm_f16<true>,  cudaFuncAttributeMaxDynamicSharedMemorySize, GEMM_SMEM);
    cudaFuncSetAttribute(gemm_f16<false>, cudaFuncAttributeMaxDynamicSharedMemorySize, GEMM_SMEM);
    cudaFuncSetAttribute(attn_mma, cudaFuncAttributeMaxDynamicSharedMemorySize, ATTN_SMEM);

    ln_kernel<<<ROWS, 256>>>(x, gamma, beta, xn);
    transpose_cvt<<<dim3(QKVW / 32, DIMD / 32), dim3(32, 8)>>>(w_qkv, wqkvT, DIMD, QKVW);
    transpose_cvt<<<dim3(DIMD / 32, INNER / 32), dim3(32, 8)>>>(w_out, woutT, INNER, DIMD);
    gemm_f16<true><<<dim3(QKVW / 128, ROWS / 128), 256, GEMM_SMEM>>>(xn, wqkvT, qkv, ROWS, QKVW, DIMD);
    attn_mma<<<dim3(SEQ / 128, HEADS, BATCH), 256, ATTN_SMEM>>>(qkv, att);
    gemm_f16<false><<<dim3(DIMD / 128, ROWS / 128), 256, GEMM_SMEM>>>(att, woutT, out, ROWS, DIMD, INNER);
}

// round 11
// speedup vs baseline: 2.3907x; 1.1193x over previous
#include <cuda_runtime.h>
#include <cuda_fp16.h>
#include <math.h>
#include <cstdint>

#define DIMD   1024
#define HEADS  16
#define DH     64
#define INNER  1024
#define BATCH  4
#define SEQ    2048
#define ROWS   (BATCH*SEQ)      // 8192
#define QKVW   (3*INNER)        // 3072

// Scratch (device globals). All fp16, NATURAL layouts.
__device__ __half g_xn   [ROWS*DIMD];
__device__ __half g_qkv  [ROWS*QKVW];
__device__ __half g_att  [ROWS*INNER];
__device__ __half g_wqkvT[QKVW*DIMD];   // [N][K]
__device__ __half g_woutT[DIMD*INNER];  // [N][K]

__device__ __forceinline__ void mma_f16(float* d, const uint32_t* a, const uint32_t* b) {
    asm volatile(
        "mma.sync.aligned.m16n8k16.row.col.f32.f16.f16.f32 "
        "{%0,%1,%2,%3}, {%4,%5,%6,%7}, {%8,%9}, {%0,%1,%2,%3};"
        : "+f"(d[0]), "+f"(d[1]), "+f"(d[2]), "+f"(d[3])
        : "r"(a[0]), "r"(a[1]), "r"(a[2]), "r"(a[3]), "r"(b[0]), "r"(b[1]));
}

__device__ __forceinline__ void ldmx4(uint32_t& r0, uint32_t& r1, uint32_t& r2,
                                      uint32_t& r3, uint32_t addr) {
    asm volatile("ldmatrix.sync.aligned.m8n8.x4.shared.b16 {%0,%1,%2,%3}, [%4];"
                 : "=r"(r0), "=r"(r1), "=r"(r2), "=r"(r3) : "r"(addr));
}
__device__ __forceinline__ void ldmx4t(uint32_t& r0, uint32_t& r1, uint32_t& r2,
                                       uint32_t& r3, uint32_t addr) {
    asm volatile("ldmatrix.sync.aligned.m8n8.x4.trans.shared.b16 {%0,%1,%2,%3}, [%4];"
                 : "=r"(r0), "=r"(r1), "=r"(r2), "=r"(r3) : "r"(addr));
}

__device__ __forceinline__ void cp_async16(uint32_t smem_dst, const void* gmem_src) {
    asm volatile("cp.async.cg.shared.global [%0], [%1], 16;" :: "r"(smem_dst), "l"(gmem_src));
}
#define CP_COMMIT() asm volatile("cp.async.commit_group;" ::: "memory")
#define CP_WAIT(n)  asm volatile("cp.async.wait_group %0;" :: "n"(n) : "memory")

__device__ __forceinline__ uint32_t h2u(__half2 h) { return *reinterpret_cast<uint32_t*>(&h); }
__device__ __forceinline__ uint32_t packh2(float a, float b) {
    return h2u(__floats2half2_rn(a, b));
}

// ===========================================================================
// LayerNorm: one block per row; OUTPUT fp16 natural.
// ===========================================================================
__global__ void ln_kernel(const float* __restrict__ x,
                          const float* __restrict__ gamma,
                          const float* __restrict__ beta,
                          __half* __restrict__ out) {
    int row = blockIdx.x;
    int tid = threadIdx.x;
    const float4* xr = reinterpret_cast<const float4*>(x + (size_t)row * DIMD);
    float4 v = xr[tid];
    float s  = v.x + v.y + v.z + v.w;
    float ss = v.x*v.x + v.y*v.y + v.z*v.z + v.w*v.w;
    #pragma unroll
    for (int o = 16; o > 0; o >>= 1) {
        s  += __shfl_xor_sync(0xFFFFFFFFu, s,  o);
        ss += __shfl_xor_sync(0xFFFFFFFFu, ss, o);
    }
    __shared__ float rs[8], rq[8];
    int w = tid >> 5, l = tid & 31;
    if (l == 0) { rs[w] = s; rq[w] = ss; }
    __syncthreads();
    if (w == 0) {
        s  = (l < 8) ? rs[l] : 0.f;
        ss = (l < 8) ? rq[l] : 0.f;
        #pragma unroll
        for (int o = 4; o > 0; o >>= 1) {
            s  += __shfl_xor_sync(0xFFFFFFFFu, s,  o);
            ss += __shfl_xor_sync(0xFFFFFFFFu, ss, o);
        }
        if (l == 0) { rs[0] = s; rq[0] = ss; }
    }
    __syncthreads();
    float mu   = rs[0] * (1.0f / DIMD);
    float var  = rq[0] * (1.0f / DIMD) - mu * mu;
    float rstd = rsqrtf(var + 1e-5f);
    float4 g4 = reinterpret_cast<const float4*>(gamma)[tid];
    float4 b4 = reinterpret_cast<const float4*>(beta)[tid];
    uint2 o2;
    o2.x = packh2((v.x - mu) * rstd * g4.x + b4.x, (v.y - mu) * rstd * g4.y + b4.y);
    o2.y = packh2((v.z - mu) * rstd * g4.z + b4.z, (v.w - mu) * rstd * g4.w + b4.w);
    *reinterpret_cast<uint2*>(out + (size_t)row * DIMD + tid * 4) = o2;
}

// ===========================================================================
// Transpose + fp16: in fp32 [R][Cc] -> out fp16 [Cc][R], natural.
// ===========================================================================
__global__ void transpose_cvt(const float* __restrict__ in, __half* __restrict__ out,
                              int R, int Cc) {
    __shared__ float t[32][33];
    int c0 = blockIdx.x * 32, r0 = blockIdx.y * 32;
    int x = threadIdx.x, y = threadIdx.y;   // 32 x 8
    #pragma unroll
    for (int i = 0; i < 32; i += 8)
        t[y + i][x] = in[(size_t)(r0 + y + i) * Cc + c0 + x];
    __syncthreads();
    #pragma unroll
    for (int i = 0; i < 32; i += 8)
        out[(size_t)(c0 + y + i) * R + r0 + x] = __float2half_rn(t[x][y + i]);
}

// ===========================================================================
// fp16 mma.sync GEMM, cp.async 2-stage, ldmatrix fragments.
// C[M,Nn] = A[M,K] @ BT[Nn,K]^T. CTA 128x128, 256 thr, warp 64x32, GBK=64.
// ===========================================================================
#define GBK   64                          // k halves per chunk
#define GSTR  72                          // row stride (halves), ldmatrix conflict-free
#define GTILE (128 * GSTR)
#define GEMM_SMEM (4 * GTILE * 2)         // 73728 B

template <bool HALF_OUT>
__global__ __launch_bounds__(256, 2)
void gemm_f16(const __half* __restrict__ A, const __half* __restrict__ BT,
              void* __restrict__ Cv, int M, int Nn, int K) {
    extern __shared__ __half smh[];

    int tid  = threadIdx.x;
    int lane = tid & 31;
    int wid  = tid >> 5;
    int wm   = wid >> 2;
    int wn   = wid & 3;

    const __half* Ab = A  + (size_t)blockIdx.y * 128 * K;
    const __half* Bb = BT + (size_t)blockIdx.x * 128 * K;

    float acc[4][4][4];
    #pragma unroll
    for (int i = 0; i < 4; i++)
        #pragma unroll
        for (int j = 0; j < 4; j++)
            #pragma unroll
            for (int k = 0; k < 4; k++) acc[i][j][k] = 0.f;

    const int nchunks = K / GBK;
    uint32_t smbase = (uint32_t)__cvta_generic_to_shared(smh);

    auto stage = [&](int c) {
        int buf = c & 1;
        uint32_t sA = smbase + (buf * GTILE) * 2;
        uint32_t sB = smbase + ((2 + buf) * GTILE) * 2;
        const __half* Ac = Ab + c * GBK;
        const __half* Bc = Bb + c * GBK;
        #pragma unroll
        for (int i = 0; i < 4; i++) {
            int idx = i * 256 + tid;           // 0..1023
            int m = idx >> 3, k8 = (idx & 7) << 3;
            cp_async16(sA + (m * GSTR + k8) * 2, Ac + (size_t)m * K + k8);
            cp_async16(sB + (m * GSTR + k8) * 2, Bc + (size_t)m * K + k8);
        }
    };

    stage(0);
    CP_COMMIT();

    int r  = lane >> 2;
    int cq = lane & 3;
    int arow = lane & 15, akoff = (lane >> 4) << 3;
    int brow = ((lane >> 4) << 3) + (lane & 7), bkoff = ((lane >> 3) & 1) << 3;

    for (int c = 0; c < nchunks; c++) {
        if (c + 1 < nchunks) {
            stage(c + 1);
            CP_COMMIT();
            CP_WAIT(1);
        } else {
            CP_WAIT(0);
        }
        __syncthreads();

        uint32_t sAu = smbase + ((c & 1) * GTILE) * 2;
        uint32_t sBu = smbase + ((2 + (c & 1)) * GTILE) * 2;

        #pragma unroll
        for (int ks = 0; ks < 4; ks++) {
            uint32_t a[4][4], b[2][4];
            #pragma unroll
            for (int mt = 0; mt < 4; mt++) {
                uint32_t addr = sAu + (((wm * 64 + mt * 16 + arow) * GSTR) + ks * 16 + akoff) * 2;
                ldmx4(a[mt][0], a[mt][1], a[mt][2], a[mt][3], addr);
            }
            #pragma unroll
            for (int np = 0; np < 2; np++) {
                uint32_t addr = sBu + (((wn * 32 + np * 16 + brow) * GSTR) + ks * 16 + bkoff) * 2;
                ldmx4(b[np][0], b[np][1], b[np][2], b[np][3], addr);
            }
            #pragma unroll
            for (int mt = 0; mt < 4; mt++)
                #pragma unroll
                for (int nt = 0; nt < 4; nt++)
                    mma_f16(acc[mt][nt], a[mt], &b[nt >> 1][(nt & 1) * 2]);
        }
        __syncthreads();
    }

    #pragma unroll
    for (int mt = 0; mt < 4; mt++) {
        int row0 = blockIdx.y * 128 + wm * 64 + mt * 16 + r;
        #pragma unroll
        for (int nt = 0; nt < 4; nt++) {
            int col0 = blockIdx.x * 128 + wn * 32 + nt * 8 + cq * 2;
            if (HALF_OUT) {
                __half* C = (__half*)Cv;
                *reinterpret_cast<uint32_t*>(C + (size_t)row0 * Nn + col0) =
                    packh2(acc[mt][nt][0], acc[mt][nt][1]);
                *reinterpret_cast<uint32_t*>(C + (size_t)(row0 + 8) * Nn + col0) =
                    packh2(acc[mt][nt][2], acc[mt][nt][3]);
            } else {
                float* C = (float*)Cv;
                *reinterpret_cast<float2*>(C + (size_t)row0 * Nn + col0) =
                    make_float2(acc[mt][nt][0], acc[mt][nt][1]);
                *reinterpret_cast<float2*>(C + (size_t)(row0 + 8) * Nn + col0) =
                    make_float2(acc[mt][nt][2], acc[mt][nt][3]);
            }
        }
    }
}

// ===========================================================================
// Flash attention fp16 mma, register-resident P. One block = (b,h),
// BQ=128, BC=64, 8 warps. K/Q frags: ldmatrix.x4; V frags: ldmatrix.x4.trans.
// ===========================================================================
#define KSTR 72
#define KTILE (64 * KSTR)                 // halves
#define ASM_Q (4 * KTILE)                 // Q after K0,K1,V0,V1
#define QSTR 72
#define ATTN_SMEM ((4 * KTILE + 128 * QSTR) * 2)   // 55296 B

__global__ __launch_bounds__(256)
void attn_mma(const __half* __restrict__ qkv, __half* __restrict__ att) {
    extern __shared__ __half smh[];

    int tid = threadIdx.x, lane = tid & 31, wid = tid >> 5;
    int r = lane >> 2, cq = lane & 3;
    int qt = gridDim.x - 1 - blockIdx.x;     // longest tiles first
    int h = blockIdx.y, b = blockIdx.z;
    int q0 = qt * 128;

    const __half* qbase = qkv + (size_t)b * SEQ * QKVW + h * DH;
    const __half* kbase = qbase + INNER;
    const __half* vbase = qbase + 2 * INNER;

    uint32_t smb = (uint32_t)__cvta_generic_to_shared(smh);
    uint32_t sQu = smb + ASM_Q * 2;

    const int nchunk = 2 * qt + 2;

    auto stage = [&](int c) {
        int buf = c & 1;
        uint32_t sK = smb + (buf * KTILE) * 2;
        uint32_t sV = smb + ((2 + buf) * KTILE) * 2;
        const __half* kc = kbase + (size_t)c * 64 * QKVW;
        const __half* vc = vbase + (size_t)c * 64 * QKVW;
        #pragma unroll
        for (int i = 0; i < 2; i++) {
            int idx = i * 256 + tid;
            int row = idx >> 3, d8 = (idx & 7) << 3;
            cp_async16(sK + (row * KSTR + d8) * 2, kc + (size_t)row * QKVW + d8);
            cp_async16(sV + (row * KSTR + d8) * 2, vc + (size_t)row * QKVW + d8);
        }
    };

    // Q tile
    #pragma unroll
    for (int i = 0; i < 4; i++) {
        int idx = i * 256 + tid;
        int row = idx >> 3, d8 = (idx & 7) << 3;
        cp_async16(sQu + (row * QSTR + d8) * 2, qbase + (size_t)(q0 + row) * QKVW + d8);
    }
    stage(0);
    CP_COMMIT();

    int arow = lane & 15, akoff = (lane >> 4) << 3;
    int brow = ((lane >> 4) << 3) + (lane & 7), bkoff = ((lane >> 3) & 1) << 3;
    int sub = lane >> 3;
    int vlb = ((sub & 1) * 8 + (lane & 7)) * KSTR + (sub >> 1) * 8;

    uint32_t qf[4][4];
    float m0 = -1e30f, m1 = -1e30f, l0 = 0.f, l1 = 0.f;
    float o[8][4];
    #pragma unroll
    for (int nt = 0; nt < 8; nt++)
        #pragma unroll
        for (int j = 0; j < 4; j++) o[nt][j] = 0.f;

    const __half2 qsc = __floats2half2_rn(0.125f, 0.125f);

    for (int c = 0; c < nchunk; c++) {
        if (c + 1 < nchunk) {
            stage(c + 1);
            CP_COMMIT();
            CP_WAIT(1);
        } else {
            CP_WAIT(0);
        }
        __syncthreads();

        if (c == 0) {
            #pragma unroll
            for (int kt = 0; kt < 4; kt++) {
                uint32_t addr = sQu + (((wid * 16 + arow) * QSTR) + kt * 16 + akoff) * 2;
                ldmx4(qf[kt][0], qf[kt][1], qf[kt][2], qf[kt][3], addr);
                #pragma unroll
                for (int j = 0; j < 4; j++)
                    qf[kt][j] = h2u(__hmul2(*reinterpret_cast<__half2*>(&qf[kt][j]), qsc));
            }
        }

        uint32_t sKu = smb + ((c & 1) * KTILE) * 2;
        uint32_t sVu = smb + ((2 + (c & 1)) * KTILE) * 2;

        int wrow0 = q0 + wid * 16;
        if (wrow0 + 15 >= c * 64) {
            float s[8][4];
            #pragma unroll
            for (int nt = 0; nt < 8; nt++)
                #pragma unroll
                for (int j = 0; j < 4; j++) s[nt][j] = 0.f;
            #pragma unroll
            for (int kt = 0; kt < 4; kt++) {
                #pragma unroll
                for (int np = 0; np < 4; np++) {
                    uint32_t b0, b1, b2, b3;
                    uint32_t addr = sKu + (((np * 16 + brow) * KSTR) + kt * 16 + bkoff) * 2;
                    ldmx4(b0, b1, b2, b3, addr);
                    uint32_t bfa[2] = { b0, b1 };
                    uint32_t bfb[2] = { b2, b3 };
                    mma_f16(s[2 * np],     qf[kt], bfa);
                    mma_f16(s[2 * np + 1], qf[kt], bfb);
                }
            }

            if (c * 64 + 63 > wrow0) {
                int row_a = wrow0 + r, row_b = wrow0 + r + 8;
                #pragma unroll
                for (int nt = 0; nt < 8; nt++) {
                    int col = c * 64 + nt * 8 + 2 * cq;
                    if (col     > row_a) s[nt][0] = -1e30f;
                    if (col + 1 > row_a) s[nt][1] = -1e30f;
                    if (col     > row_b) s[nt][2] = -1e30f;
                    if (col + 1 > row_b) s[nt][3] = -1e30f;
                }
            }

            float mt0 = -1e30f, mt1 = -1e30f;
            #pragma unroll
            for (int nt = 0; nt < 8; nt++) {
                mt0 = fmaxf(mt0, fmaxf(s[nt][0], s[nt][1]));
                mt1 = fmaxf(mt1, fmaxf(s[nt][2], s[nt][3]));
            }
            mt0 = fmaxf(mt0, __shfl_xor_sync(0xFFFFFFFFu, mt0, 1));
            mt0 = fmaxf(mt0, __shfl_xor_sync(0xFFFFFFFFu, mt0, 2));
            mt1 = fmaxf(mt1, __shfl_xor_sync(0xFFFFFFFFu, mt1, 1));
            mt1 = fmaxf(mt1, __shfl_xor_sync(0xFFFFFFFFu, mt1, 2));

            float mn0 = fmaxf(m0, mt0), mn1 = fmaxf(m1, mt1);
            float a0 = __expf(m0 - mn0), a1 = __expf(m1 - mn1);
            m0 = mn0; m1 = mn1;
            float rs0 = 0.f, rs1 = 0.f;
            #pragma unroll
            for (int nt = 0; nt < 8; nt++) {
                s[nt][0] = __expf(s[nt][0] - mn0);
                s[nt][1] = __expf(s[nt][1] - mn0);
                s[nt][2] = __expf(s[nt][2] - mn1);
                s[nt][3] = __expf(s[nt][3] - mn1);
                rs0 += s[nt][0] + s[nt][1];
                rs1 += s[nt][2] + s[nt][3];
            }
            rs0 += __shfl_xor_sync(0xFFFFFFFFu, rs0, 1);
            rs0 += __shfl_xor_sync(0xFFFFFFFFu, rs0, 2);
            rs1 += __shfl_xor_sync(0xFFFFFFFFu, rs1, 1);
            rs1 += __shfl_xor_sync(0xFFFFFFFFu, rs1, 2);
            l0 = l0 * a0 + rs0;
            l1 = l1 * a1 + rs1;
            #pragma unroll
            for (int nt = 0; nt < 8; nt++) {
                o[nt][0] *= a0; o[nt][1] *= a0;
                o[nt][2] *= a1; o[nt][3] *= a1;
            }

            #pragma unroll
            for (int kt = 0; kt < 4; kt++) {
                uint32_t pf[4];
                pf[0] = packh2(s[2 * kt][0],     s[2 * kt][1]);
                pf[1] = packh2(s[2 * kt][2],     s[2 * kt][3]);
                pf[2] = packh2(s[2 * kt + 1][0], s[2 * kt + 1][1]);
                pf[3] = packh2(s[2 * kt + 1][2], s[2 * kt + 1][3]);
                #pragma unroll
                for (int ntp = 0; ntp < 4; ntp++) {
                    uint32_t b0a, b1a, b0b, b1b;
                    uint32_t addr = sVu + (vlb + kt * 16 * KSTR + ntp * 16) * 2;
                    ldmx4t(b0a, b1a, b0b, b1b, addr);
                    uint32_t bfa[2] = { b0a, b1a };
                    uint32_t bfb[2] = { b0b, b1b };
                    mma_f16(o[2 * ntp],     pf, bfa);
                    mma_f16(o[2 * ntp + 1], pf, bfb);
                }
            }
        }
        __syncthreads();
    }

    float inv0 = 1.f / l0, inv1 = 1.f / l1;
    int row_a = q0 + wid * 16 + r, row_b = row_a + 8;
    #pragma unroll
    for (int nt = 0; nt < 8; nt++) {
        int col = h * DH + nt * 8 + 2 * cq;
        *reinterpret_cast<uint32_t*>(att + ((size_t)b * SEQ + row_a) * INNER + col) =
            packh2(o[nt][0] * inv0, o[nt][1] * inv0);
        *reinterpret_cast<uint32_t*>(att + ((size_t)b * SEQ + row_b) * INNER + col) =
            packh2(o[nt][2] * inv1, o[nt][3] * inv1);
    }
}

// ===========================================================================
extern "C" void kernel_launch(void* const* d_in, const int* in_sizes, int n_in,
                              void* d_out, int out_size) {
    const float* x     = (const float*)d_in[0];
    const float* gamma = (const float*)d_in[1];
    const float* beta  = (const float*)d_in[2];
    const float* w_qkv = (const float*)d_in[3];
    const float* w_out = (const float*)d_in[4];
    float* out = (float*)d_out;

    __half *xn, *qkv, *att, *wqkvT, *woutT;
    cudaGetSymbolAddress((void**)&xn,    g_xn);
    cudaGetSymbolAddress((void**)&qkv,   g_qkv);
    cudaGetSymbolAddress((void**)&att,   g_att);
    cudaGetSymbolAddress((void**)&wqkvT, g_wqkvT);
    cudaGetSymbolAddress((void**)&woutT, g_woutT);

    cudaFuncSetAttribute(gemm_f16<true>,  cudaFuncAttributeMaxDynamicSharedMemorySize, GEMM_SMEM);
    cudaFuncSetAttribute(gemm_f16<false>, cudaFuncAttributeMaxDynamicSharedMemorySize, GEMM_SMEM);
    cudaFuncSetAttribute(attn_mma, cudaFuncAttributeMaxDynamicSharedMemorySize, ATTN_SMEM);

    ln_kernel<<<ROWS, 256>>>(x, gamma, beta, xn);
    transpose_cvt<<<dim3(QKVW / 32, DIMD / 32), dim3(32, 8)>>>(w_qkv, wqkvT, DIMD, QKVW);
    transpose_cvt<<<dim3(DIMD / 32, INNER / 32), dim3(32, 8)>>>(w_out, woutT, INNER, DIMD);
    gemm_f16<true><<<dim3(QKVW / 128, ROWS / 128), 256, GEMM_SMEM>>>(xn, wqkvT, qkv, ROWS, QKVW, DIMD);
    attn_mma<<<dim3(SEQ / 128, HEADS, BATCH), 256, ATTN_SMEM>>>(qkv, att);
    gemm_f16<false><<<dim3(DIMD / 128, ROWS / 128), 256, GEMM_SMEM>>>(att, woutT, out, ROWS, DIMD, INNER);
}